// round 15
// baseline (speedup 1.0000x reference)
#include <cuda_runtime.h>
#include <cuda_fp16.h>
#include <math.h>
#include <stdint.h>

// ---------------- problem constants ----------------
constexpr int Bb   = 32;
constexpr int Nn   = 196;
constexpr int Cc   = 768;
constexpr int Hh   = 12;
constexpr int Ll   = 4;
constexpr int DFF  = 3072;
constexpr int HD   = Cc / Hh;          // 64
constexpr int ROWS = Bb * Nn;          // 6272
constexpr int NCAT = 2 * Nn;           // 392

// weight sizes per stream (elements)
constexpr int W_QKV = Cc * 3 * Cc;
constexpr int W_PRJ = Cc * Cc;
constexpr int W_FC1 = Cc * DFF;
constexpr int W_FC2 = DFF * Cc;
constexpr int W_ALL = W_QKV + W_PRJ + W_FC1 + W_FC2;
constexpr int W_HALF = W_ALL / 2;      // u32 per stream

// ---------------- scratch (static device memory; no allocation) ----------------
__device__ float    g_fused[Bb * Ll * Cc];
__device__ __half   g_h   [2 * ROWS * Cc];       // LN out (half, k-permuted)
__device__ __half   g_qkv [2 * ROWS * 3 * Cc];   // qkv out (half, natural)
__device__ __half   g_o   [2 * ROWS * Cc];       // attn out (half, k-permuted)
__device__ __half   g_mlp [2 * ROWS * DFF];      // gelu out (half, k-permuted)
__device__ uint32_t g_w   [W_ALL];               // 2 streams x W_HALF u32 (half2-packed)

// k-permutation within a 16-group: memory pos order = [2t,2t+1,2t+8,2t+9] for t=0..3.
__device__ __forceinline__ int permA(int c) {
    const int w = c & 15;
    return (c & ~15) | (((w & 7) >> 1) << 2) | ((w >> 3) << 1) | (w & 1);
}

// ============================================================================
// ALL weights -> half2-packed u32, n-permuted, ONE launch.
// ============================================================================
__global__ void round_w_all_kernel(const float* __restrict__ sq, const float* __restrict__ spj,
                                   const float* __restrict__ s1, const float* __restrict__ s2,
                                   const float* __restrict__ rq, const float* __restrict__ rpj,
                                   const float* __restrict__ r1, const float* __restrict__ r2,
                                   uint32_t* __restrict__ out)
{
    int i = blockIdx.x * blockDim.x + threadIdx.x;
    if (i >= W_ALL) return;
    const int s = i / W_HALF;
    int j = i - s * W_HALF;

    const float* in;
    int N;
    if (j < W_QKV / 2)                      { in = s ? rq : sq;   N = 3 * Cc; }
    else if (j < (W_QKV + W_PRJ) / 2)       { in = s ? rpj : spj; N = Cc;     j -= W_QKV / 2; }
    else if (j < (W_QKV + W_PRJ + W_FC1)/2) { in = s ? r1 : s1;   N = DFF;    j -= (W_QKV + W_PRJ) / 2; }
    else                                    { in = s ? r2 : s2;   N = Cc;     j -= (W_QKV + W_PRJ + W_FC1) / 2; }

    int kp = j / N, ps = j - kp * N;
    int p = ps & 31;
    int n = (ps & ~31) + ((p & 3) << 3) + (p >> 2);
    float lo = in[(size_t)(2 * kp) * N + n];
    float hi = in[(size_t)(2 * kp + 1) * N + n];
    __half2 h = __floats2half2_rn(lo, hi);
    out[i] = *(uint32_t*)&h;
}

// ============================================================================
// fused latents = sdpa(latents, concat(x,y), concat(x,y), C^-0.5)
// ============================================================================
__global__ void fuse_latents_kernel(const float* __restrict__ x,
                                    const float* __restrict__ y,
                                    const float* __restrict__ lat,
                                    float* __restrict__ fused)
{
    const int b = blockIdx.x;
    const int tid = threadIdx.x, lane = tid & 31, w = tid >> 5;

    __shared__ float slat[Ll * Cc];
    __shared__ float s[Ll][NCAT];

    for (int i = tid; i < Ll * Cc; i += 256) slat[i] = lat[i];
    __syncthreads();

    const float scale = 0.03608439182435161f;  // 1/sqrt(768)

    for (int n = w; n < NCAT; n += 8) {
        const float* row = (n < Nn) ? x + (size_t)(b * Nn + n) * Cc
                                    : y + (size_t)(b * Nn + (n - Nn)) * Cc;
        float a0 = 0.f, a1 = 0.f, a2 = 0.f, a3 = 0.f;
        for (int c = lane; c < Cc; c += 32) {
            float v = row[c];
            a0 += slat[c] * v;
            a1 += slat[Cc + c] * v;
            a2 += slat[2 * Cc + c] * v;
            a3 += slat[3 * Cc + c] * v;
        }
        #pragma unroll
        for (int o = 16; o; o >>= 1) {
            a0 += __shfl_xor_sync(0xffffffffu, a0, o);
            a1 += __shfl_xor_sync(0xffffffffu, a1, o);
            a2 += __shfl_xor_sync(0xffffffffu, a2, o);
            a3 += __shfl_xor_sync(0xffffffffu, a3, o);
        }
        if (lane == 0) {
            s[0][n] = a0 * scale; s[1][n] = a1 * scale;
            s[2][n] = a2 * scale; s[3][n] = a3 * scale;
        }
    }
    __syncthreads();

    if (w < Ll) {
        float mx = -INFINITY;
        for (int n = lane; n < NCAT; n += 32) mx = fmaxf(mx, s[w][n]);
        #pragma unroll
        for (int o = 16; o; o >>= 1) mx = fmaxf(mx, __shfl_xor_sync(0xffffffffu, mx, o));
        float sum = 0.f;
        for (int n = lane; n < NCAT; n += 32) {
            float e = __expf(s[w][n] - mx);
            s[w][n] = e;
            sum += e;
        }
        #pragma unroll
        for (int o = 16; o; o >>= 1) sum += __shfl_xor_sync(0xffffffffu, sum, o);
        const float inv = 1.f / sum;
        for (int n = lane; n < NCAT; n += 32) s[w][n] *= inv;
    }
    __syncthreads();

    float acc[Ll][3];
    #pragma unroll
    for (int l = 0; l < Ll; l++) { acc[l][0] = acc[l][1] = acc[l][2] = 0.f; }

    const float* xb = x + (size_t)b * Nn * Cc;
    const float* yb = y + (size_t)b * Nn * Cc;
    #pragma unroll 2
    for (int n = 0; n < Nn; n++) {
        const float* row = xb + (size_t)n * Cc;
        float v0 = row[tid], v1 = row[tid + 256], v2 = row[tid + 512];
        #pragma unroll
        for (int l = 0; l < Ll; l++) {
            float sl = s[l][n];
            acc[l][0] += sl * v0; acc[l][1] += sl * v1; acc[l][2] += sl * v2;
        }
    }
    #pragma unroll 2
    for (int n = 0; n < Nn; n++) {
        const float* row = yb + (size_t)n * Cc;
        float v0 = row[tid], v1 = row[tid + 256], v2 = row[tid + 512];
        #pragma unroll
        for (int l = 0; l < Ll; l++) {
            float sl = s[l][Nn + n];
            acc[l][0] += sl * v0; acc[l][1] += sl * v1; acc[l][2] += sl * v2;
        }
    }
    #pragma unroll
    for (int l = 0; l < Ll; l++) {
        float* fp = fused + (size_t)(b * Ll + l) * Cc;
        fp[tid] = acc[l][0]; fp[tid + 256] = acc[l][1]; fp[tid + 512] = acc[l][2];
    }
}

// ============================================================================
// FUSED: out = in + scale * sdpa(in, fused, fused, C^-0.5);  h = LN1(out) half
// ============================================================================
__global__ void cross_attend_ln_kernel(const float* __restrict__ x,
                                       const float* __restrict__ y,
                                       const float* __restrict__ fused,
                                       const float* __restrict__ scale_a,
                                       const float* __restrict__ scale_v,
                                       const float* __restrict__ g0, const float* __restrict__ b0,
                                       const float* __restrict__ g1, const float* __restrict__ b1,
                                       float* __restrict__ outb,
                                       __half* __restrict__ hb)
{
    const int row = blockIdx.x;
    const int b = row / Nn;
    const int z = blockIdx.y;
    const int tid = threadIdx.x, lane = tid & 31, w = tid >> 5;

    const float* in = (z ? y : x) + (size_t)row * Cc;
    float* out = outb + ((size_t)z * ROWS + row) * Cc;
    __half* hout = hb + ((size_t)z * ROWS + row) * Cc;
    const float sc = z ? *scale_v : *scale_a;
    const float* g   = z ? g1 : g0;
    const float* bta = z ? b1 : b0;
    const float* f = fused + (size_t)b * Ll * Cc;

    __shared__ float red[32];
    __shared__ float w4[Ll];
    __shared__ float sred[8];

    const float v0 = in[tid], v1 = in[tid + 256], v2 = in[tid + 512];

    float p[4];
    #pragma unroll
    for (int l = 0; l < Ll; l++) {
        const float* fl = f + l * Cc;
        p[l] = v0 * fl[tid] + v1 * fl[tid + 256] + v2 * fl[tid + 512];
    }
    #pragma unroll
    for (int o = 16; o; o >>= 1) {
        p[0] += __shfl_xor_sync(0xffffffffu, p[0], o);
        p[1] += __shfl_xor_sync(0xffffffffu, p[1], o);
        p[2] += __shfl_xor_sync(0xffffffffu, p[2], o);
        p[3] += __shfl_xor_sync(0xffffffffu, p[3], o);
    }
    if (lane == 0) {
        red[w * 4 + 0] = p[0]; red[w * 4 + 1] = p[1];
        red[w * 4 + 2] = p[2]; red[w * 4 + 3] = p[3];
    }
    __syncthreads();
    if (tid == 0) {
        float t[4] = {0.f, 0.f, 0.f, 0.f};
        #pragma unroll
        for (int i = 0; i < 8; i++) {
            t[0] += red[i * 4]; t[1] += red[i * 4 + 1];
            t[2] += red[i * 4 + 2]; t[3] += red[i * 4 + 3];
        }
        const float scale = 0.03608439182435161f;
        float s0 = t[0] * scale, s1 = t[1] * scale, s2 = t[2] * scale, s3 = t[3] * scale;
        float mx = fmaxf(fmaxf(s0, s1), fmaxf(s2, s3));
        float e0 = __expf(s0 - mx), e1 = __expf(s1 - mx);
        float e2 = __expf(s2 - mx), e3 = __expf(s3 - mx);
        float inv = 1.f / (e0 + e1 + e2 + e3);
        w4[0] = e0 * inv; w4[1] = e1 * inv; w4[2] = e2 * inv; w4[3] = e3 * inv;
    }
    __syncthreads();

    const float a0 = w4[0], a1 = w4[1], a2 = w4[2], a3 = w4[3];
    float o0 = v0 + sc * (a0 * f[tid]       + a1 * f[Cc + tid]       + a2 * f[2 * Cc + tid]       + a3 * f[3 * Cc + tid]);
    float o1 = v1 + sc * (a0 * f[tid + 256] + a1 * f[Cc + tid + 256] + a2 * f[2 * Cc + tid + 256] + a3 * f[3 * Cc + tid + 256]);
    float o2 = v2 + sc * (a0 * f[tid + 512] + a1 * f[Cc + tid + 512] + a2 * f[2 * Cc + tid + 512] + a3 * f[3 * Cc + tid + 512]);
    out[tid] = o0; out[tid + 256] = o1; out[tid + 512] = o2;

    float sum = o0 + o1 + o2;
    #pragma unroll
    for (int o = 16; o; o >>= 1) sum += __shfl_xor_sync(0xffffffffu, sum, o);
    if (lane == 0) sred[w] = sum;
    __syncthreads();
    float mean = 0.f;
    #pragma unroll
    for (int i = 0; i < 8; i++) mean += sred[i];
    mean *= (1.f / Cc);
    __syncthreads();

    float d0 = o0 - mean, d1 = o1 - mean, d2 = o2 - mean;
    float var = d0 * d0 + d1 * d1 + d2 * d2;
    #pragma unroll
    for (int o = 16; o; o >>= 1) var += __shfl_xor_sync(0xffffffffu, var, o);
    if (lane == 0) sred[w] = var;
    __syncthreads();
    float vs = 0.f;
    #pragma unroll
    for (int i = 0; i < 8; i++) vs += sred[i];
    const float rstd = rsqrtf(vs * (1.f / Cc) + 1e-6f);

    hout[permA(tid)]       = __float2half_rn(d0 * rstd * g[tid]       + bta[tid]);
    hout[permA(tid + 256)] = __float2half_rn(d1 * rstd * g[tid + 256] + bta[tid + 256]);
    hout[permA(tid + 512)] = __float2half_rn(d2 * rstd * g[tid + 512] + bta[tid + 512]);
}

// ============================================================================
// LayerNorm (LN2)
// ============================================================================
__global__ void ln_kernel(const float* __restrict__ inb,
                          const float* __restrict__ g0, const float* __restrict__ b0,
                          const float* __restrict__ g1, const float* __restrict__ b1,
                          __half* __restrict__ outb)
{
    const int z = blockIdx.y;
    const int row = blockIdx.x;
    const int tid = threadIdx.x, lane = tid & 31, w = tid >> 5;
    const float* g   = z ? g1 : g0;
    const float* bta = z ? b1 : b0;
    const float* ip = inb  + ((size_t)z * ROWS + row) * Cc;
    __half*      op = outb + ((size_t)z * ROWS + row) * Cc;

    __shared__ float sred[8];

    float v0 = ip[tid], v1 = ip[tid + 256], v2 = ip[tid + 512];
    float sum = v0 + v1 + v2;
    #pragma unroll
    for (int o = 16; o; o >>= 1) sum += __shfl_xor_sync(0xffffffffu, sum, o);
    if (lane == 0) sred[w] = sum;
    __syncthreads();
    float mean = 0.f;
    #pragma unroll
    for (int i = 0; i < 8; i++) mean += sred[i];
    mean *= (1.f / Cc);
    __syncthreads();

    float d0 = v0 - mean, d1 = v1 - mean, d2 = v2 - mean;
    float var = d0 * d0 + d1 * d1 + d2 * d2;
    #pragma unroll
    for (int o = 16; o; o >>= 1) var += __shfl_xor_sync(0xffffffffu, var, o);
    if (lane == 0) sred[w] = var;
    __syncthreads();
    float vs = 0.f;
    #pragma unroll
    for (int i = 0; i < 8; i++) vs += sred[i];
    const float rstd = rsqrtf(vs * (1.f / Cc) + 1e-6f);

    op[permA(tid)]       = __float2half_rn(d0 * rstd * g[tid]       + bta[tid]);
    op[permA(tid + 256)] = __float2half_rn(d1 * rstd * g[tid + 256] + bta[tid + 256]);
    op[permA(tid + 512)] = __float2half_rn(d2 * rstd * g[tid + 512] + bta[tid + 512]);
}

// ============================================================================
// FP16 tensor-core GEMM: 128x128 block, 8 warps (2x4) at 64x32, m16n8k16,
// fp32 acc. Stage = 2 k-tiles (K-step 32), 3 stages / prefetch distance 2,
// race-free tail, cp.async.cg. __launch_bounds__(256,3) -> 3 CTAs/SM (24 warps).
// EPI: 0 = bias f32, 1 = bias+gelu half permA, 2 = bias+residual f32,
//      3 = bias half natural (qkv).
// ============================================================================
constexpr int LDBW = 136;
constexpr int A_TILE_H = 128 * 16;
constexpr int B_TILE_W = 8 * LDBW;
constexpr int A_TILE_BYTES = A_TILE_H * 2;        // 4096
constexpr int B_TILE_BYTES = B_TILE_W * 4;        // 4352
constexpr int A_STG_BYTES = 2 * A_TILE_BYTES;     // 8192
constexpr int B_STG_BYTES = 2 * B_TILE_BYTES;     // 8704
constexpr int STAGES = 3;
constexpr int GEMM_SMEM = STAGES * (A_STG_BYTES + B_STG_BYTES);  // 50688

__device__ __forceinline__ void cp_async16(uint32_t s, const void* g) {
    asm volatile("cp.async.cg.shared.global [%0], [%1], 16;" :: "r"(s), "l"(g));
}
__device__ __forceinline__ void cp_commit() {
    asm volatile("cp.async.commit_group;");
}
template<int N>
__device__ __forceinline__ void cp_wait() {
    asm volatile("cp.async.wait_group %0;" :: "n"(N));
}

__device__ __forceinline__ void mma_f16(float* d, uint32_t a0, uint32_t a1,
                                        uint32_t a2, uint32_t a3,
                                        uint32_t b0, uint32_t b1) {
    asm volatile(
        "mma.sync.aligned.m16n8k16.row.col.f32.f16.f16.f32 "
        "{%0,%1,%2,%3}, {%4,%5,%6,%7}, {%8,%9}, {%0,%1,%2,%3};"
        : "+f"(d[0]), "+f"(d[1]), "+f"(d[2]), "+f"(d[3])
        : "r"(a0), "r"(a1), "r"(a2), "r"(a3), "r"(b0), "r"(b1));
}

template<int EPI>
__global__ __launch_bounds__(256, 3)
void h16_gemm_kernel(const __half* __restrict__ Abase, size_t strideA,
                     const uint32_t* __restrict__ W0, const uint32_t* __restrict__ W1,
                     const float* __restrict__ bias0, const float* __restrict__ bias1,
                     const float* __restrict__ resbase,
                     void* __restrict__ Cbase, size_t strideC,
                     int M, int N, int K)
{
    extern __shared__ char smem[];
    char* Ar = smem;
    char* Br = smem + STAGES * A_STG_BYTES;

    const int z = blockIdx.z;
    const __half* A     = Abase + (size_t)z * strideA;
    const uint32_t* Wm  = z ? W1 : W0;
    const float* bias   = z ? bias1 : bias0;
    const float* res    = (EPI == 2) ? resbase + (size_t)z * strideC : nullptr;
    float*  Cf = (float*)Cbase + (size_t)z * strideC;
    __half* Ch = (__half*)Cbase + (size_t)z * strideC;

    const int tid  = threadIdx.x;
    const int lane = tid & 31;
    const int w    = tid >> 5;
    const int wm   = w >> 2;
    const int wn   = w & 3;
    const int gid  = lane >> 2;
    const int tig  = lane & 3;

    const int bm = blockIdx.y * 128;
    const int bn = blockIdx.x * 128;

    float acc[4][4][4];
    #pragma unroll
    for (int i = 0; i < 4; i++)
        #pragma unroll
        for (int j = 0; j < 4; j++)
            #pragma unroll
            for (int q = 0; q < 4; q++) acc[i][j][q] = 0.f;

    const int arow = tid >> 1;
    const int achk = tid & 1;
    const int bkp  = tid >> 5;
    const int bcol = (tid & 31) * 4;

    const __half* Ap = A + (size_t)(bm + arow) * K + achk * 8;
    const uint32_t* Bp = Wm + (size_t)bkp * N + bn + bcol;

    const uint32_t sA = (uint32_t)__cvta_generic_to_shared(Ar) + arow * 32 + achk * 16;
    const uint32_t sB = (uint32_t)__cvta_generic_to_shared(Br) + (bkp * LDBW + bcol) * 4;

    // per-warp fragment base offsets (hoisted; bytes)
    const int aoff = ((wm * 64 + gid) * 16 + tig * 4) * 2;
    const int boff = (wn * 32 + gid * 4) * 4;

    const int KT2 = K / 32;

    auto load_stage = [&](int k2, int stg) {
        #pragma unroll
        for (int sub = 0; sub < 2; sub++) {
            const int kt = k2 * 2 + sub;
            cp_async16(sA + stg * A_STG_BYTES + sub * A_TILE_BYTES, Ap + kt * 16);
            cp_async16(sB + stg * B_STG_BYTES + sub * B_TILE_BYTES, Bp + (size_t)kt * 8 * N);
        }
        cp_commit();
    };

    load_stage(0, 0);
    load_stage(1, 1);
    cp_wait<1>();
    __syncthreads();

    int buf = 0;
    for (int k2 = 0; k2 < KT2; k2++) {
        const bool pf = (k2 + 2 < KT2);
        if (pf) {
            int s = buf + 2; if (s >= STAGES) s -= STAGES;
            load_stage(k2 + 2, s);
        }

        const char* Abase_s = Ar + buf * A_STG_BYTES + aoff;
        const char* Bbase_s = Br + buf * B_STG_BYTES + boff;
        #pragma unroll
        for (int sub = 0; sub < 2; sub++) {
            const __half*   Aw = (const __half*)(Abase_s + sub * A_TILE_BYTES);
            const uint32_t* Bw = (const uint32_t*)(Bbase_s + sub * B_TILE_BYTES);

            uint4 bq0 = *(const uint4*)(Bw + tig * LDBW);
            uint4 bq1 = *(const uint4*)(Bw + (tig + 4) * LDBW);

            #pragma unroll
            for (int i = 0; i < 4; i++) {
                uint2 aLo = *(const uint2*)(Aw + i * 256);
                uint2 aHi = *(const uint2*)(Aw + i * 256 + 128);
                mma_f16(acc[i][0], aLo.x, aHi.x, aLo.y, aHi.y, bq0.x, bq1.x);
                mma_f16(acc[i][1], aLo.x, aHi.x, aLo.y, aHi.y, bq0.y, bq1.y);
                mma_f16(acc[i][2], aLo.x, aHi.x, aLo.y, aHi.y, bq0.z, bq1.z);
                mma_f16(acc[i][3], aLo.x, aHi.x, aLo.y, aHi.y, bq0.w, bq1.w);
            }
        }

        if (k2 + 1 < KT2) {
            if (pf) cp_wait<1>(); else cp_wait<0>();   // race-free tail
            __syncthreads();
            buf = (buf + 1 < STAGES) ? buf + 1 : 0;
        }
    }

    #pragma unroll
    for (int i = 0; i < 4; i++) {
        const int r0 = bm + wm * 64 + i * 16 + gid;
        #pragma unroll
        for (int j = 0; j < 4; j++) {
            const int c = bn + wn * 32 + j * 8 + tig * 2;
            const float b0 = bias[c], b1 = bias[c + 1];

            float v0 = acc[i][j][0] + b0;
            float v1 = acc[i][j][1] + b1;
            float v2 = acc[i][j][2] + b0;
            float v3 = acc[i][j][3] + b1;
            if (EPI == 1) {
                v0 = v0 * 0.5f * (1.f + erff(v0 * 0.70710678118654752f));
                v1 = v1 * 0.5f * (1.f + erff(v1 * 0.70710678118654752f));
                v2 = v2 * 0.5f * (1.f + erff(v2 * 0.70710678118654752f));
                v3 = v3 * 0.5f * (1.f + erff(v3 * 0.70710678118654752f));
                const int pa = permA(c);
                *(__half2*)&Ch[(size_t)r0 * N + pa]       = __floats2half2_rn(v0, v1);
                *(__half2*)&Ch[(size_t)(r0 + 8) * N + pa] = __floats2half2_rn(v2, v3);
            } else if (EPI == 3) {
                *(__half2*)&Ch[(size_t)r0 * N + c]       = __floats2half2_rn(v0, v1);
                *(__half2*)&Ch[(size_t)(r0 + 8) * N + c] = __floats2half2_rn(v2, v3);
            } else {
                if (EPI == 2) {
                    const float* r = res + (size_t)r0 * N + c;
                    v0 += r[0]; v1 += r[1];
                    const float* r2 = res + (size_t)(r0 + 8) * N + c;
                    v2 += r2[0]; v3 += r2[1];
                }
                *(float2*)&Cf[(size_t)r0 * N + c]       = make_float2(v0, v1);
                *(float2*)&Cf[(size_t)(r0 + 8) * N + c] = make_float2(v2, v3);
            }
        }
    }
}

// ============================================================================
// Attention: reads HALF qkv, fp32 internals; output half, k-permuted
// ============================================================================
constexpr int KST = HD + 4;                      // 68
constexpr int VST = Nn + 8;                      // 204
constexpr int ATTN_SMEM = (Nn * KST + HD * VST + 8 * Nn + 8 * HD) * 4;

__global__ void attn_kernel(const __half* __restrict__ qkvb_, __half* __restrict__ ob_)
{
    extern __shared__ float sm[];
    float* Ks = sm;
    float* Vt = Ks + Nn * KST;
    float* S  = Vt + HD * VST;
    float* Qs = S + 8 * Nn;

    const int z = blockIdx.y;
    const int bh = blockIdx.x;
    const int b = bh / Hh, hh = bh % Hh;
    const int tid = threadIdx.x, lane = tid & 31, w = tid >> 5;

    const __half* qkvb = qkvb_ + (size_t)z * ROWS * 3 * Cc + (size_t)b * Nn * (3 * Cc);
    __half* o = ob_ + (size_t)z * ROWS * Cc;

    for (int idx = tid; idx < Nn * HD; idx += 256) {
        const int n = idx >> 6, d = idx & 63;
        const __half* rp = qkvb + (size_t)n * (3 * Cc) + hh * HD + d;
        Ks[n * KST + d] = __half2float(rp[Cc]);
        Vt[d * VST + n] = __half2float(rp[2 * Cc]);
    }
    __syncthreads();

    float* Sw = S + w * Nn;
    float* Qw = Qs + w * HD;

    for (int r = w; r < Nn; r += 8) {
        const __half* qp = qkvb + (size_t)r * (3 * Cc) + hh * HD;
        Qw[lane] = __half2float(qp[lane]);
        Qw[lane + 32] = __half2float(qp[lane + 32]);
        __syncwarp();

        float q[HD];
        #pragma unroll
        for (int d = 0; d < HD; d++) q[d] = Qw[d];

        float mx = -INFINITY;
        for (int k = lane; k < Nn; k += 32) {
            const float* kr = &Ks[k * KST];
            float acc = 0.f;
            #pragma unroll
            for (int c = 0; c < HD / 4; c++) {
                float4 kk = *(const float4*)(kr + c * 4);
                acc = fmaf(q[4 * c],     kk.x, acc);
                acc = fmaf(q[4 * c + 1], kk.y, acc);
                acc = fmaf(q[4 * c + 2], kk.z, acc);
                acc = fmaf(q[4 * c + 3], kk.w, acc);
            }
            acc *= 0.125f;
            Sw[k] = acc;
            mx = fmaxf(mx, acc);
        }
        #pragma unroll
        for (int off = 16; off; off >>= 1) mx = fmaxf(mx, __shfl_xor_sync(0xffffffffu, mx, off));

        float sum = 0.f;
        for (int k = lane; k < Nn; k += 32) {
            float e = __expf(Sw[k] - mx);
            Sw[k] = e;
            sum += e;
        }
        #pragma unroll
        for (int off = 16; off; off >>= 1) sum += __shfl_xor_sync(0xffffffffu, sum, off);
        const float inv = 1.f / sum;
        __syncwarp();

        const float* v0r = &Vt[lane * VST];
        const float* v1r = &Vt[(lane + 32) * VST];
        float a0 = 0.f, a1 = 0.f;
        #pragma unroll 7
        for (int k0 = 0; k0 < Nn; k0 += 4) {
            float4 p  = *(const float4*)&Sw[k0];
            float4 u0 = *(const float4*)(v0r + k0);
            float4 u1 = *(const float4*)(v1r + k0);
            a0 += p.x * u0.x + p.y * u0.y + p.z * u0.z + p.w * u0.w;
            a1 += p.x * u1.x + p.y * u1.y + p.z * u1.z + p.w * u1.w;
        }
        __half* op = o + (size_t)(b * Nn + r) * Cc;
        const int c0 = hh * HD + lane;
        op[permA(c0)]      = __float2half_rn(a0 * inv);
        op[permA(c0 + 32)] = __float2half_rn(a1 * inv);
        __syncwarp();
    }
}

// ============================================================================
// host launcher
// ============================================================================
extern "C" void kernel_launch(void* const* d_in, const int* in_sizes, int n_in,
                              void* d_out, int out_size)
{
    const float* x        = (const float*)d_in[0];
    const float* y        = (const float*)d_in[1];
    const float* latents  = (const float*)d_in[2];
    const float* scale_a  = (const float*)d_in[3];
    const float* scale_v  = (const float*)d_in[4];

    const float* sp[12];
    const float* rp[12];
    for (int i = 0; i < 12; i++) { sp[i] = (const float*)d_in[5 + i]; rp[i] = (const float*)d_in[17 + i]; }

    float* outx = (float*)d_out;

    float *fused;
    __half *hbuf, *qkvbuf, *obuf, *mlpbuf;
    uint32_t* wbuf;
    cudaGetSymbolAddress((void**)&fused,  g_fused);
    cudaGetSymbolAddress((void**)&hbuf,   g_h);
    cudaGetSymbolAddress((void**)&qkvbuf, g_qkv);
    cudaGetSymbolAddress((void**)&obuf,   g_o);
    cudaGetSymbolAddress((void**)&mlpbuf, g_mlp);
    cudaGetSymbolAddress((void**)&wbuf,   g_w);

    // smem opt-in (GEMM 50688 B, attn 111 KB > 48 KB default)
    cudaFuncSetAttribute(attn_kernel, cudaFuncAttributeMaxDynamicSharedMemorySize, ATTN_SMEM);
    cudaFuncSetAttribute(h16_gemm_kernel<0>, cudaFuncAttributeMaxDynamicSharedMemorySize, GEMM_SMEM);
    cudaFuncSetAttribute(h16_gemm_kernel<1>, cudaFuncAttributeMaxDynamicSharedMemorySize, GEMM_SMEM);
    cudaFuncSetAttribute(h16_gemm_kernel<2>, cudaFuncAttributeMaxDynamicSharedMemorySize, GEMM_SMEM);
    cudaFuncSetAttribute(h16_gemm_kernel<3>, cudaFuncAttributeMaxDynamicSharedMemorySize, GEMM_SMEM);

    const size_t sC   = (size_t)ROWS * Cc;
    const size_t sQKV = (size_t)ROWS * 3 * Cc;
    const size_t sMLP = (size_t)ROWS * DFF;

    uint32_t* wq[2]; uint32_t* wp[2]; uint32_t* w1[2]; uint32_t* w2[2];
    for (int s = 0; s < 2; s++) {
        uint32_t* base = wbuf + (size_t)s * W_HALF;
        wq[s] = base;
        wp[s] = base + W_QKV / 2;
        w1[s] = base + (W_QKV + W_PRJ) / 2;
        w2[s] = base + (W_QKV + W_PRJ + W_FC1) / 2;
    }

    // launch order: #4 = qkv GEMM (ncu captures the 4th launch)
    round_w_all_kernel<<<(W_ALL + 255) / 256, 256>>>(
        sp[2], sp[4], sp[8], sp[10], rp[2], rp[4], rp[8], rp[10], wbuf);

    fuse_latents_kernel<<<Bb, 256>>>(x, y, latents, fused);

    cross_attend_ln_kernel<<<dim3(ROWS, 2), 256>>>(
        x, y, fused, scale_a, scale_v,
        sp[0], sp[1], rp[0], rp[1], outx, hbuf);

    h16_gemm_kernel<3><<<dim3(3 * Cc / 128, ROWS / 128, 2), 256, GEMM_SMEM>>>(
        hbuf, sC, wq[0], wq[1], sp[3], rp[3], nullptr, qkvbuf, sQKV,
        ROWS, 3 * Cc, Cc);

    attn_kernel<<<dim3(Bb * Hh, 2), 256, ATTN_SMEM>>>(qkvbuf, obuf);

    h16_gemm_kernel<2><<<dim3(Cc / 128, ROWS / 128, 2), 256, GEMM_SMEM>>>(
        obuf, sC, wp[0], wp[1], sp[5], rp[5], outx, outx, sC,
        ROWS, Cc, Cc);

    ln_kernel<<<dim3(ROWS, 2), 256>>>(outx, sp[6], sp[7], rp[6], rp[7], hbuf);

    h16_gemm_kernel<1><<<dim3(DFF / 128, ROWS / 128, 2), 256, GEMM_SMEM>>>(
        hbuf, sC, w1[0], w1[1], sp[9], rp[9], nullptr, mlpbuf, sMLP,
        ROWS, DFF, Cc);

    h16_gemm_kernel<2><<<dim3(Cc / 128, ROWS / 128, 2), 256, GEMM_SMEM>>>(
        mlpbuf, sMLP, w2[0], w2[1], sp[11], rp[11], outx, outx, sC,
        ROWS, Cc, DFF);
}

// round 16
// speedup vs baseline: 1.2665x; 1.2665x over previous
#include <cuda_runtime.h>
#include <cuda_fp16.h>
#include <math.h>
#include <stdint.h>

// ---------------- problem constants ----------------
constexpr int Bb   = 32;
constexpr int Nn   = 196;
constexpr int Cc   = 768;
constexpr int Hh   = 12;
constexpr int Ll   = 4;
constexpr int DFF  = 3072;
constexpr int HD   = Cc / Hh;          // 64
constexpr int ROWS = Bb * Nn;          // 6272
constexpr int NCAT = 2 * Nn;           // 392

// weight sizes per stream (elements)
constexpr int W_QKV = Cc * 3 * Cc;
constexpr int W_PRJ = Cc * Cc;
constexpr int W_FC1 = Cc * DFF;
constexpr int W_FC2 = DFF * Cc;
constexpr int W_ALL = W_QKV + W_PRJ + W_FC1 + W_FC2;
constexpr int W_HALF = W_ALL / 2;      // u32 per stream

// ---------------- scratch (static device memory; no allocation) ----------------
__device__ float    g_fused[Bb * Ll * Cc];
__device__ __half   g_h   [2 * ROWS * Cc];       // LN out (half, k-permuted)
__device__ __half   g_qkv [2 * ROWS * 3 * Cc];   // qkv out (half, natural)
__device__ __half   g_o   [2 * ROWS * Cc];       // attn out (half, k-permuted)
__device__ __half   g_mlp [2 * ROWS * DFF];      // gelu out (half, k-permuted)
__device__ uint32_t g_w   [W_ALL];               // 2 streams x W_HALF u32 (half2-packed)

// k-permutation within a 16-group: memory pos order = [2t,2t+1,2t+8,2t+9] for t=0..3.
__device__ __forceinline__ int permA(int c) {
    const int w = c & 15;
    return (c & ~15) | (((w & 7) >> 1) << 2) | ((w >> 3) << 1) | (w & 1);
}

// ============================================================================
// ALL weights -> half2-packed u32, n-permuted, ONE launch.
// ============================================================================
__global__ void round_w_all_kernel(const float* __restrict__ sq, const float* __restrict__ spj,
                                   const float* __restrict__ s1, const float* __restrict__ s2,
                                   const float* __restrict__ rq, const float* __restrict__ rpj,
                                   const float* __restrict__ r1, const float* __restrict__ r2,
                                   uint32_t* __restrict__ out)
{
    int i = blockIdx.x * blockDim.x + threadIdx.x;
    if (i >= W_ALL) return;
    const int s = i / W_HALF;
    int j = i - s * W_HALF;

    const float* in;
    int N;
    if (j < W_QKV / 2)                      { in = s ? rq : sq;   N = 3 * Cc; }
    else if (j < (W_QKV + W_PRJ) / 2)       { in = s ? rpj : spj; N = Cc;     j -= W_QKV / 2; }
    else if (j < (W_QKV + W_PRJ + W_FC1)/2) { in = s ? r1 : s1;   N = DFF;    j -= (W_QKV + W_PRJ) / 2; }
    else                                    { in = s ? r2 : s2;   N = Cc;     j -= (W_QKV + W_PRJ + W_FC1) / 2; }

    int kp = j / N, ps = j - kp * N;
    int p = ps & 31;
    int n = (ps & ~31) + ((p & 3) << 3) + (p >> 2);
    float lo = in[(size_t)(2 * kp) * N + n];
    float hi = in[(size_t)(2 * kp + 1) * N + n];
    __half2 h = __floats2half2_rn(lo, hi);
    out[i] = *(uint32_t*)&h;
}

// ============================================================================
// fused latents = sdpa(latents, concat(x,y), concat(x,y), C^-0.5)
// ============================================================================
__global__ void fuse_latents_kernel(const float* __restrict__ x,
                                    const float* __restrict__ y,
                                    const float* __restrict__ lat,
                                    float* __restrict__ fused)
{
    const int b = blockIdx.x;
    const int tid = threadIdx.x, lane = tid & 31, w = tid >> 5;

    __shared__ float slat[Ll * Cc];
    __shared__ float s[Ll][NCAT];

    for (int i = tid; i < Ll * Cc; i += 256) slat[i] = lat[i];
    __syncthreads();

    const float scale = 0.03608439182435161f;  // 1/sqrt(768)

    for (int n = w; n < NCAT; n += 8) {
        const float* row = (n < Nn) ? x + (size_t)(b * Nn + n) * Cc
                                    : y + (size_t)(b * Nn + (n - Nn)) * Cc;
        float a0 = 0.f, a1 = 0.f, a2 = 0.f, a3 = 0.f;
        for (int c = lane; c < Cc; c += 32) {
            float v = row[c];
            a0 += slat[c] * v;
            a1 += slat[Cc + c] * v;
            a2 += slat[2 * Cc + c] * v;
            a3 += slat[3 * Cc + c] * v;
        }
        #pragma unroll
        for (int o = 16; o; o >>= 1) {
            a0 += __shfl_xor_sync(0xffffffffu, a0, o);
            a1 += __shfl_xor_sync(0xffffffffu, a1, o);
            a2 += __shfl_xor_sync(0xffffffffu, a2, o);
            a3 += __shfl_xor_sync(0xffffffffu, a3, o);
        }
        if (lane == 0) {
            s[0][n] = a0 * scale; s[1][n] = a1 * scale;
            s[2][n] = a2 * scale; s[3][n] = a3 * scale;
        }
    }
    __syncthreads();

    if (w < Ll) {
        float mx = -INFINITY;
        for (int n = lane; n < NCAT; n += 32) mx = fmaxf(mx, s[w][n]);
        #pragma unroll
        for (int o = 16; o; o >>= 1) mx = fmaxf(mx, __shfl_xor_sync(0xffffffffu, mx, o));
        float sum = 0.f;
        for (int n = lane; n < NCAT; n += 32) {
            float e = __expf(s[w][n] - mx);
            s[w][n] = e;
            sum += e;
        }
        #pragma unroll
        for (int o = 16; o; o >>= 1) sum += __shfl_xor_sync(0xffffffffu, sum, o);
        const float inv = 1.f / sum;
        for (int n = lane; n < NCAT; n += 32) s[w][n] *= inv;
    }
    __syncthreads();

    float acc[Ll][3];
    #pragma unroll
    for (int l = 0; l < Ll; l++) { acc[l][0] = acc[l][1] = acc[l][2] = 0.f; }

    const float* xb = x + (size_t)b * Nn * Cc;
    const float* yb = y + (size_t)b * Nn * Cc;
    #pragma unroll 2
    for (int n = 0; n < Nn; n++) {
        const float* row = xb + (size_t)n * Cc;
        float v0 = row[tid], v1 = row[tid + 256], v2 = row[tid + 512];
        #pragma unroll
        for (int l = 0; l < Ll; l++) {
            float sl = s[l][n];
            acc[l][0] += sl * v0; acc[l][1] += sl * v1; acc[l][2] += sl * v2;
        }
    }
    #pragma unroll 2
    for (int n = 0; n < Nn; n++) {
        const float* row = yb + (size_t)n * Cc;
        float v0 = row[tid], v1 = row[tid + 256], v2 = row[tid + 512];
        #pragma unroll
        for (int l = 0; l < Ll; l++) {
            float sl = s[l][Nn + n];
            acc[l][0] += sl * v0; acc[l][1] += sl * v1; acc[l][2] += sl * v2;
        }
    }
    #pragma unroll
    for (int l = 0; l < Ll; l++) {
        float* fp = fused + (size_t)(b * Ll + l) * Cc;
        fp[tid] = acc[l][0]; fp[tid + 256] = acc[l][1]; fp[tid + 512] = acc[l][2];
    }
}

// ============================================================================
// FUSED: out = in + scale * sdpa(in, fused, fused, C^-0.5);  h = LN1(out) half
// ============================================================================
__global__ void cross_attend_ln_kernel(const float* __restrict__ x,
                                       const float* __restrict__ y,
                                       const float* __restrict__ fused,
                                       const float* __restrict__ scale_a,
                                       const float* __restrict__ scale_v,
                                       const float* __restrict__ g0, const float* __restrict__ b0,
                                       const float* __restrict__ g1, const float* __restrict__ b1,
                                       float* __restrict__ outb,
                                       __half* __restrict__ hb)
{
    const int row = blockIdx.x;
    const int b = row / Nn;
    const int z = blockIdx.y;
    const int tid = threadIdx.x, lane = tid & 31, w = tid >> 5;

    const float* in = (z ? y : x) + (size_t)row * Cc;
    float* out = outb + ((size_t)z * ROWS + row) * Cc;
    __half* hout = hb + ((size_t)z * ROWS + row) * Cc;
    const float sc = z ? *scale_v : *scale_a;
    const float* g   = z ? g1 : g0;
    const float* bta = z ? b1 : b0;
    const float* f = fused + (size_t)b * Ll * Cc;

    __shared__ float red[32];
    __shared__ float w4[Ll];
    __shared__ float sred[8];

    const float v0 = in[tid], v1 = in[tid + 256], v2 = in[tid + 512];

    float p[4];
    #pragma unroll
    for (int l = 0; l < Ll; l++) {
        const float* fl = f + l * Cc;
        p[l] = v0 * fl[tid] + v1 * fl[tid + 256] + v2 * fl[tid + 512];
    }
    #pragma unroll
    for (int o = 16; o; o >>= 1) {
        p[0] += __shfl_xor_sync(0xffffffffu, p[0], o);
        p[1] += __shfl_xor_sync(0xffffffffu, p[1], o);
        p[2] += __shfl_xor_sync(0xffffffffu, p[2], o);
        p[3] += __shfl_xor_sync(0xffffffffu, p[3], o);
    }
    if (lane == 0) {
        red[w * 4 + 0] = p[0]; red[w * 4 + 1] = p[1];
        red[w * 4 + 2] = p[2]; red[w * 4 + 3] = p[3];
    }
    __syncthreads();
    if (tid == 0) {
        float t[4] = {0.f, 0.f, 0.f, 0.f};
        #pragma unroll
        for (int i = 0; i < 8; i++) {
            t[0] += red[i * 4]; t[1] += red[i * 4 + 1];
            t[2] += red[i * 4 + 2]; t[3] += red[i * 4 + 3];
        }
        const float scale = 0.03608439182435161f;
        float s0 = t[0] * scale, s1 = t[1] * scale, s2 = t[2] * scale, s3 = t[3] * scale;
        float mx = fmaxf(fmaxf(s0, s1), fmaxf(s2, s3));
        float e0 = __expf(s0 - mx), e1 = __expf(s1 - mx);
        float e2 = __expf(s2 - mx), e3 = __expf(s3 - mx);
        float inv = 1.f / (e0 + e1 + e2 + e3);
        w4[0] = e0 * inv; w4[1] = e1 * inv; w4[2] = e2 * inv; w4[3] = e3 * inv;
    }
    __syncthreads();

    const float a0 = w4[0], a1 = w4[1], a2 = w4[2], a3 = w4[3];
    float o0 = v0 + sc * (a0 * f[tid]       + a1 * f[Cc + tid]       + a2 * f[2 * Cc + tid]       + a3 * f[3 * Cc + tid]);
    float o1 = v1 + sc * (a0 * f[tid + 256] + a1 * f[Cc + tid + 256] + a2 * f[2 * Cc + tid + 256] + a3 * f[3 * Cc + tid + 256]);
    float o2 = v2 + sc * (a0 * f[tid + 512] + a1 * f[Cc + tid + 512] + a2 * f[2 * Cc + tid + 512] + a3 * f[3 * Cc + tid + 512]);
    out[tid] = o0; out[tid + 256] = o1; out[tid + 512] = o2;

    float sum = o0 + o1 + o2;
    #pragma unroll
    for (int o = 16; o; o >>= 1) sum += __shfl_xor_sync(0xffffffffu, sum, o);
    if (lane == 0) sred[w] = sum;
    __syncthreads();
    float mean = 0.f;
    #pragma unroll
    for (int i = 0; i < 8; i++) mean += sred[i];
    mean *= (1.f / Cc);
    __syncthreads();

    float d0 = o0 - mean, d1 = o1 - mean, d2 = o2 - mean;
    float var = d0 * d0 + d1 * d1 + d2 * d2;
    #pragma unroll
    for (int o = 16; o; o >>= 1) var += __shfl_xor_sync(0xffffffffu, var, o);
    if (lane == 0) sred[w] = var;
    __syncthreads();
    float vs = 0.f;
    #pragma unroll
    for (int i = 0; i < 8; i++) vs += sred[i];
    const float rstd = rsqrtf(vs * (1.f / Cc) + 1e-6f);

    hout[permA(tid)]       = __float2half_rn(d0 * rstd * g[tid]       + bta[tid]);
    hout[permA(tid + 256)] = __float2half_rn(d1 * rstd * g[tid + 256] + bta[tid + 256]);
    hout[permA(tid + 512)] = __float2half_rn(d2 * rstd * g[tid + 512] + bta[tid + 512]);
}

// ============================================================================
// LayerNorm (LN2)
// ============================================================================
__global__ void ln_kernel(const float* __restrict__ inb,
                          const float* __restrict__ g0, const float* __restrict__ b0,
                          const float* __restrict__ g1, const float* __restrict__ b1,
                          __half* __restrict__ outb)
{
    const int z = blockIdx.y;
    const int row = blockIdx.x;
    const int tid = threadIdx.x, lane = tid & 31, w = tid >> 5;
    const float* g   = z ? g1 : g0;
    const float* bta = z ? b1 : b0;
    const float* ip = inb  + ((size_t)z * ROWS + row) * Cc;
    __half*      op = outb + ((size_t)z * ROWS + row) * Cc;

    __shared__ float sred[8];

    float v0 = ip[tid], v1 = ip[tid + 256], v2 = ip[tid + 512];
    float sum = v0 + v1 + v2;
    #pragma unroll
    for (int o = 16; o; o >>= 1) sum += __shfl_xor_sync(0xffffffffu, sum, o);
    if (lane == 0) sred[w] = sum;
    __syncthreads();
    float mean = 0.f;
    #pragma unroll
    for (int i = 0; i < 8; i++) mean += sred[i];
    mean *= (1.f / Cc);
    __syncthreads();

    float d0 = v0 - mean, d1 = v1 - mean, d2 = v2 - mean;
    float var = d0 * d0 + d1 * d1 + d2 * d2;
    #pragma unroll
    for (int o = 16; o; o >>= 1) var += __shfl_xor_sync(0xffffffffu, var, o);
    if (lane == 0) sred[w] = var;
    __syncthreads();
    float vs = 0.f;
    #pragma unroll
    for (int i = 0; i < 8; i++) vs += sred[i];
    const float rstd = rsqrtf(vs * (1.f / Cc) + 1e-6f);

    op[permA(tid)]       = __float2half_rn(d0 * rstd * g[tid]       + bta[tid]);
    op[permA(tid + 256)] = __float2half_rn(d1 * rstd * g[tid + 256] + bta[tid + 256]);
    op[permA(tid + 512)] = __float2half_rn(d2 * rstd * g[tid + 512] + bta[tid + 512]);
}

// ============================================================================
// FP16 tensor-core GEMM (R14-measured best): 128x128 block, 8 warps (2x4) at
// 64x32, m16n8k16, fp32 acc. Stage = 2 k-tiles (K-step 32), 3 stages /
// prefetch distance 2, race-free tail, cp.async.cg, 2 CTAs/SM.
// EPI: 0 = bias f32, 1 = bias+gelu half permA, 2 = bias+residual f32,
//      3 = bias half natural (qkv).
// ============================================================================
constexpr int LDBW = 136;
constexpr int A_TILE_H = 128 * 16;
constexpr int B_TILE_W = 8 * LDBW;
constexpr int A_TILE_BYTES = A_TILE_H * 2;        // 4096
constexpr int B_TILE_BYTES = B_TILE_W * 4;        // 4352
constexpr int A_STG_BYTES = 2 * A_TILE_BYTES;     // 8192
constexpr int B_STG_BYTES = 2 * B_TILE_BYTES;     // 8704
constexpr int STAGES = 3;
constexpr int GEMM_SMEM = STAGES * (A_STG_BYTES + B_STG_BYTES);  // 50688

__device__ __forceinline__ void cp_async16(uint32_t s, const void* g) {
    asm volatile("cp.async.cg.shared.global [%0], [%1], 16;" :: "r"(s), "l"(g));
}
__device__ __forceinline__ void cp_commit() {
    asm volatile("cp.async.commit_group;");
}
template<int N>
__device__ __forceinline__ void cp_wait() {
    asm volatile("cp.async.wait_group %0;" :: "n"(N));
}

__device__ __forceinline__ void mma_f16(float* d, uint32_t a0, uint32_t a1,
                                        uint32_t a2, uint32_t a3,
                                        uint32_t b0, uint32_t b1) {
    asm volatile(
        "mma.sync.aligned.m16n8k16.row.col.f32.f16.f16.f32 "
        "{%0,%1,%2,%3}, {%4,%5,%6,%7}, {%8,%9}, {%0,%1,%2,%3};"
        : "+f"(d[0]), "+f"(d[1]), "+f"(d[2]), "+f"(d[3])
        : "r"(a0), "r"(a1), "r"(a2), "r"(a3), "r"(b0), "r"(b1));
}

template<int EPI>
__global__ __launch_bounds__(256, 2)
void h16_gemm_kernel(const __half* __restrict__ Abase, size_t strideA,
                     const uint32_t* __restrict__ W0, const uint32_t* __restrict__ W1,
                     const float* __restrict__ bias0, const float* __restrict__ bias1,
                     const float* __restrict__ resbase,
                     void* __restrict__ Cbase, size_t strideC,
                     int M, int N, int K)
{
    extern __shared__ char smem[];
    char* Ar = smem;
    char* Br = smem + STAGES * A_STG_BYTES;

    const int z = blockIdx.z;
    const __half* A     = Abase + (size_t)z * strideA;
    const uint32_t* Wm  = z ? W1 : W0;
    const float* bias   = z ? bias1 : bias0;
    const float* res    = (EPI == 2) ? resbase + (size_t)z * strideC : nullptr;
    float*  Cf = (float*)Cbase + (size_t)z * strideC;
    __half* Ch = (__half*)Cbase + (size_t)z * strideC;

    const int tid  = threadIdx.x;
    const int lane = tid & 31;
    const int w    = tid >> 5;
    const int wm   = w >> 2;
    const int wn   = w & 3;
    const int gid  = lane >> 2;
    const int tig  = lane & 3;

    const int bm = blockIdx.y * 128;
    const int bn = blockIdx.x * 128;

    float acc[4][4][4];
    #pragma unroll
    for (int i = 0; i < 4; i++)
        #pragma unroll
        for (int j = 0; j < 4; j++)
            #pragma unroll
            for (int q = 0; q < 4; q++) acc[i][j][q] = 0.f;

    const int arow = tid >> 1;
    const int achk = tid & 1;
    const int bkp  = tid >> 5;
    const int bcol = (tid & 31) * 4;

    const __half* Ap = A + (size_t)(bm + arow) * K + achk * 8;
    const uint32_t* Bp = Wm + (size_t)bkp * N + bn + bcol;

    const uint32_t sA = (uint32_t)__cvta_generic_to_shared(Ar) + arow * 32 + achk * 16;
    const uint32_t sB = (uint32_t)__cvta_generic_to_shared(Br) + (bkp * LDBW + bcol) * 4;

    // per-warp fragment base offsets (bytes)
    const int aoff = ((wm * 64 + gid) * 16 + tig * 4) * 2;
    const int boff = (wn * 32 + gid * 4) * 4;

    const int KT2 = K / 32;

    auto load_stage = [&](int k2, int stg) {
        #pragma unroll
        for (int sub = 0; sub < 2; sub++) {
            const int kt = k2 * 2 + sub;
            cp_async16(sA + stg * A_STG_BYTES + sub * A_TILE_BYTES, Ap + kt * 16);
            cp_async16(sB + stg * B_STG_BYTES + sub * B_TILE_BYTES, Bp + (size_t)kt * 8 * N);
        }
        cp_commit();
    };

    load_stage(0, 0);
    load_stage(1, 1);
    cp_wait<1>();
    __syncthreads();

    int buf = 0;
    for (int k2 = 0; k2 < KT2; k2++) {
        const bool pf = (k2 + 2 < KT2);
        if (pf) {
            int s = buf + 2; if (s >= STAGES) s -= STAGES;
            load_stage(k2 + 2, s);
        }

        const char* Abase_s = Ar + buf * A_STG_BYTES + aoff;
        const char* Bbase_s = Br + buf * B_STG_BYTES + boff;
        #pragma unroll
        for (int sub = 0; sub < 2; sub++) {
            const __half*   Aw = (const __half*)(Abase_s + sub * A_TILE_BYTES);
            const uint32_t* Bw = (const uint32_t*)(Bbase_s + sub * B_TILE_BYTES);

            uint4 bq0 = *(const uint4*)(Bw + tig * LDBW);
            uint4 bq1 = *(const uint4*)(Bw + (tig + 4) * LDBW);

            #pragma unroll
            for (int i = 0; i < 4; i++) {
                uint2 aLo = *(const uint2*)(Aw + i * 256);
                uint2 aHi = *(const uint2*)(Aw + i * 256 + 128);
                mma_f16(acc[i][0], aLo.x, aHi.x, aLo.y, aHi.y, bq0.x, bq1.x);
                mma_f16(acc[i][1], aLo.x, aHi.x, aLo.y, aHi.y, bq0.y, bq1.y);
                mma_f16(acc[i][2], aLo.x, aHi.x, aLo.y, aHi.y, bq0.z, bq1.z);
                mma_f16(acc[i][3], aLo.x, aHi.x, aLo.y, aHi.y, bq0.w, bq1.w);
            }
        }

        if (k2 + 1 < KT2) {
            if (pf) cp_wait<1>(); else cp_wait<0>();   // race-free tail
            __syncthreads();
            buf = (buf + 1 < STAGES) ? buf + 1 : 0;
        }
    }

    #pragma unroll
    for (int i = 0; i < 4; i++) {
        const int r0 = bm + wm * 64 + i * 16 + gid;
        #pragma unroll
        for (int j = 0; j < 4; j++) {
            const int c = bn + wn * 32 + j * 8 + tig * 2;
            const float b0 = bias[c], b1 = bias[c + 1];

            float v0 = acc[i][j][0] + b0;
            float v1 = acc[i][j][1] + b1;
            float v2 = acc[i][j][2] + b0;
            float v3 = acc[i][j][3] + b1;
            if (EPI == 1) {
                v0 = v0 * 0.5f * (1.f + erff(v0 * 0.70710678118654752f));
                v1 = v1 * 0.5f * (1.f + erff(v1 * 0.70710678118654752f));
                v2 = v2 * 0.5f * (1.f + erff(v2 * 0.70710678118654752f));
                v3 = v3 * 0.5f * (1.f + erff(v3 * 0.70710678118654752f));
                const int pa = permA(c);
                *(__half2*)&Ch[(size_t)r0 * N + pa]       = __floats2half2_rn(v0, v1);
                *(__half2*)&Ch[(size_t)(r0 + 8) * N + pa] = __floats2half2_rn(v2, v3);
            } else if (EPI == 3) {
                *(__half2*)&Ch[(size_t)r0 * N + c]       = __floats2half2_rn(v0, v1);
                *(__half2*)&Ch[(size_t)(r0 + 8) * N + c] = __floats2half2_rn(v2, v3);
            } else {
                if (EPI == 2) {
                    const float* r = res + (size_t)r0 * N + c;
                    v0 += r[0]; v1 += r[1];
                    const float* r2 = res + (size_t)(r0 + 8) * N + c;
                    v2 += r2[0]; v3 += r2[1];
                }
                *(float2*)&Cf[(size_t)r0 * N + c]       = make_float2(v0, v1);
                *(float2*)&Cf[(size_t)(r0 + 8) * N + c] = make_float2(v2, v3);
            }
        }
    }
}

// ============================================================================
// Attention: reads HALF qkv (half2-vectorized fill), fp32 internals;
// output half, k-permuted
// ============================================================================
constexpr int KST = HD + 4;                      // 68
constexpr int VST = Nn + 8;                      // 204
constexpr int ATTN_SMEM = (Nn * KST + HD * VST + 8 * Nn + 8 * HD) * 4;

__global__ void attn_kernel(const __half* __restrict__ qkvb_, __half* __restrict__ ob_)
{
    extern __shared__ float sm[];
    float* Ks = sm;
    float* Vt = Ks + Nn * KST;
    float* S  = Vt + HD * VST;
    float* Qs = S + 8 * Nn;

    const int z = blockIdx.y;
    const int bh = blockIdx.x;
    const int b = bh / Hh, hh = bh % Hh;
    const int tid = threadIdx.x, lane = tid & 31, w = tid >> 5;

    const __half* qkvb = qkvb_ + (size_t)z * ROWS * 3 * Cc + (size_t)b * Nn * (3 * Cc);
    __half* o = ob_ + (size_t)z * ROWS * Cc;

    // half2-vectorized K/V smem fill
    for (int idx = tid; idx < Nn * (HD / 2); idx += 256) {
        const int n = idx >> 5, d = (idx & 31) * 2;
        const __half* rp = qkvb + (size_t)n * (3 * Cc) + hh * HD + d;
        float2 kf = __half22float2(*(const __half2*)(rp + Cc));
        float2 vf = __half22float2(*(const __half2*)(rp + 2 * Cc));
        *(float2*)&Ks[n * KST + d] = kf;
        Vt[d * VST + n] = vf.x;
        Vt[(d + 1) * VST + n] = vf.y;
    }
    __syncthreads();

    float* Sw = S + w * Nn;
    float* Qw = Qs + w * HD;

    for (int r = w; r < Nn; r += 8) {
        const __half* qp = qkvb + (size_t)r * (3 * Cc) + hh * HD;
        Qw[lane] = __half2float(qp[lane]);
        Qw[lane + 32] = __half2float(qp[lane + 32]);
        __syncwarp();

        float q[HD];
        #pragma unroll
        for (int d = 0; d < HD; d++) q[d] = Qw[d];

        float mx = -INFINITY;
        for (int k = lane; k < Nn; k += 32) {
            const float* kr = &Ks[k * KST];
            float acc = 0.f;
            #pragma unroll
            for (int c = 0; c < HD / 4; c++) {
                float4 kk = *(const float4*)(kr + c * 4);
                acc = fmaf(q[4 * c],     kk.x, acc);
                acc = fmaf(q[4 * c + 1], kk.y, acc);
                acc = fmaf(q[4 * c + 2], kk.z, acc);
                acc = fmaf(q[4 * c + 3], kk.w, acc);
            }
            acc *= 0.125f;
            Sw[k] = acc;
            mx = fmaxf(mx, acc);
        }
        #pragma unroll
        for (int off = 16; off; off >>= 1) mx = fmaxf(mx, __shfl_xor_sync(0xffffffffu, mx, off));

        float sum = 0.f;
        for (int k = lane; k < Nn; k += 32) {
            float e = __expf(Sw[k] - mx);
            Sw[k] = e;
            sum += e;
        }
        #pragma unroll
        for (int off = 16; off; off >>= 1) sum += __shfl_xor_sync(0xffffffffu, sum, off);
        const float inv = 1.f / sum;
        __syncwarp();

        const float* v0r = &Vt[lane * VST];
        const float* v1r = &Vt[(lane + 32) * VST];
        float a0 = 0.f, a1 = 0.f;
        #pragma unroll 7
        for (int k0 = 0; k0 < Nn; k0 += 4) {
            float4 p  = *(const float4*)&Sw[k0];
            float4 u0 = *(const float4*)(v0r + k0);
            float4 u1 = *(const float4*)(v1r + k0);
            a0 += p.x * u0.x + p.y * u0.y + p.z * u0.z + p.w * u0.w;
            a1 += p.x * u1.x + p.y * u1.y + p.z * u1.z + p.w * u1.w;
        }
        __half* op = o + (size_t)(b * Nn + r) * Cc;
        const int c0 = hh * HD + lane;
        op[permA(c0)]      = __float2half_rn(a0 * inv);
        op[permA(c0 + 32)] = __float2half_rn(a1 * inv);
        __syncwarp();
    }
}

// ============================================================================
// host launcher
// ============================================================================
extern "C" void kernel_launch(void* const* d_in, const int* in_sizes, int n_in,
                              void* d_out, int out_size)
{
    const float* x        = (const float*)d_in[0];
    const float* y        = (const float*)d_in[1];
    const float* latents  = (const float*)d_in[2];
    const float* scale_a  = (const float*)d_in[3];
    const float* scale_v  = (const float*)d_in[4];

    const float* sp[12];
    const float* rp[12];
    for (int i = 0; i < 12; i++) { sp[i] = (const float*)d_in[5 + i]; rp[i] = (const float*)d_in[17 + i]; }

    float* outx = (float*)d_out;

    float *fused;
    __half *hbuf, *qkvbuf, *obuf, *mlpbuf;
    uint32_t* wbuf;
    cudaGetSymbolAddress((void**)&fused,  g_fused);
    cudaGetSymbolAddress((void**)&hbuf,   g_h);
    cudaGetSymbolAddress((void**)&qkvbuf, g_qkv);
    cudaGetSymbolAddress((void**)&obuf,   g_o);
    cudaGetSymbolAddress((void**)&mlpbuf, g_mlp);
    cudaGetSymbolAddress((void**)&wbuf,   g_w);

    // smem opt-in (GEMM 50688 B, attn 111 KB > 48 KB default)
    cudaFuncSetAttribute(attn_kernel, cudaFuncAttributeMaxDynamicSharedMemorySize, ATTN_SMEM);
    cudaFuncSetAttribute(h16_gemm_kernel<0>, cudaFuncAttributeMaxDynamicSharedMemorySize, GEMM_SMEM);
    cudaFuncSetAttribute(h16_gemm_kernel<1>, cudaFuncAttributeMaxDynamicSharedMemorySize, GEMM_SMEM);
    cudaFuncSetAttribute(h16_gemm_kernel<2>, cudaFuncAttributeMaxDynamicSharedMemorySize, GEMM_SMEM);
    cudaFuncSetAttribute(h16_gemm_kernel<3>, cudaFuncAttributeMaxDynamicSharedMemorySize, GEMM_SMEM);

    const size_t sC   = (size_t)ROWS * Cc;
    const size_t sQKV = (size_t)ROWS * 3 * Cc;
    const size_t sMLP = (size_t)ROWS * DFF;

    uint32_t* wq[2]; uint32_t* wp[2]; uint32_t* w1[2]; uint32_t* w2[2];
    for (int s = 0; s < 2; s++) {
        uint32_t* base = wbuf + (size_t)s * W_HALF;
        wq[s] = base;
        wp[s] = base + W_QKV / 2;
        w1[s] = base + (W_QKV + W_PRJ) / 2;
        w2[s] = base + (W_QKV + W_PRJ + W_FC1) / 2;
    }

    // launch order: #4 = qkv GEMM (ncu captures the 4th launch)
    round_w_all_kernel<<<(W_ALL + 255) / 256, 256>>>(
        sp[2], sp[4], sp[8], sp[10], rp[2], rp[4], rp[8], rp[10], wbuf);

    fuse_latents_kernel<<<Bb, 256>>>(x, y, latents, fused);

    cross_attend_ln_kernel<<<dim3(ROWS, 2), 256>>>(
        x, y, fused, scale_a, scale_v,
        sp[0], sp[1], rp[0], rp[1], outx, hbuf);

    h16_gemm_kernel<3><<<dim3(3 * Cc / 128, ROWS / 128, 2), 256, GEMM_SMEM>>>(
        hbuf, sC, wq[0], wq[1], sp[3], rp[3], nullptr, qkvbuf, sQKV,
        ROWS, 3 * Cc, Cc);

    attn_kernel<<<dim3(Bb * Hh, 2), 256, ATTN_SMEM>>>(qkvbuf, obuf);

    h16_gemm_kernel<2><<<dim3(Cc / 128, ROWS / 128, 2), 256, GEMM_SMEM>>>(
        obuf, sC, wp[0], wp[1], sp[5], rp[5], outx, outx, sC,
        ROWS, Cc, Cc);

    ln_kernel<<<dim3(ROWS, 2), 256>>>(outx, sp[6], sp[7], rp[6], rp[7], hbuf);

    h16_gemm_kernel<1><<<dim3(DFF / 128, ROWS / 128, 2), 256, GEMM_SMEM>>>(
        hbuf, sC, w1[0], w1[1], sp[9], rp[9], nullptr, mlpbuf, sMLP,
        ROWS, DFF, Cc);

    h16_gemm_kernel<2><<<dim3(Cc / 128, ROWS / 128, 2), 256, GEMM_SMEM>>>(
        mlpbuf, sMLP, w2[0], w2[1], sp[11], rp[11], outx, outx, sC,
        ROWS, Cc, DFF);
}

// round 17
// speedup vs baseline: 1.8140x; 1.4323x over previous
#include <cuda_runtime.h>
#include <cuda_fp16.h>
#include <math.h>
#include <stdint.h>

// ---------------- problem constants ----------------
constexpr int Bb   = 32;
constexpr int Nn   = 196;
constexpr int Cc   = 768;
constexpr int Hh   = 12;
constexpr int Ll   = 4;
constexpr int DFF  = 3072;
constexpr int HD   = Cc / Hh;          // 64
constexpr int ROWS = Bb * Nn;          // 6272
constexpr int NCAT = 2 * Nn;           // 392

// weight sizes per stream (elements)
constexpr int W_QKV = Cc * 3 * Cc;
constexpr int W_PRJ = Cc * Cc;
constexpr int W_FC1 = Cc * DFF;
constexpr int W_FC2 = DFF * Cc;
constexpr int W_ALL = W_QKV + W_PRJ + W_FC1 + W_FC2;
constexpr int W_HALF = W_ALL / 2;      // u32 per stream

// ---------------- scratch (static device memory; no allocation) ----------------
__device__ float    g_fused[Bb * Ll * Cc];
__device__ __half   g_h   [2 * ROWS * Cc];       // LN out (half, k-permuted)
__device__ __half   g_qkv [2 * ROWS * 3 * Cc];   // qkv out (half, natural)
__device__ __half   g_o   [2 * ROWS * Cc];       // attn out (half, k-permuted)
__device__ __half   g_mlp [2 * ROWS * DFF];      // gelu out (half, k-permuted)
__device__ uint32_t g_w   [W_ALL];               // 2 streams x W_HALF u32 (half2-packed)

// k-permutation within a 16-group: memory pos order = [2t,2t+1,2t+8,2t+9] for t=0..3.
__device__ __forceinline__ int permA(int c) {
    const int w = c & 15;
    return (c & ~15) | (((w & 7) >> 1) << 2) | ((w >> 3) << 1) | (w & 1);
}

__device__ __forceinline__ void mma_f16(float* d, uint32_t a0, uint32_t a1,
                                        uint32_t a2, uint32_t a3,
                                        uint32_t b0, uint32_t b1) {
    asm volatile(
        "mma.sync.aligned.m16n8k16.row.col.f32.f16.f16.f32 "
        "{%0,%1,%2,%3}, {%4,%5,%6,%7}, {%8,%9}, {%0,%1,%2,%3};"
        : "+f"(d[0]), "+f"(d[1]), "+f"(d[2]), "+f"(d[3])
        : "r"(a0), "r"(a1), "r"(a2), "r"(a3), "r"(b0), "r"(b1));
}

// ============================================================================
// ALL weights -> half2-packed u32, n-permuted, ONE launch.
// ============================================================================
__global__ void round_w_all_kernel(const float* __restrict__ sq, const float* __restrict__ spj,
                                   const float* __restrict__ s1, const float* __restrict__ s2,
                                   const float* __restrict__ rq, const float* __restrict__ rpj,
                                   const float* __restrict__ r1, const float* __restrict__ r2,
                                   uint32_t* __restrict__ out)
{
    int i = blockIdx.x * blockDim.x + threadIdx.x;
    if (i >= W_ALL) return;
    const int s = i / W_HALF;
    int j = i - s * W_HALF;

    const float* in;
    int N;
    if (j < W_QKV / 2)                      { in = s ? rq : sq;   N = 3 * Cc; }
    else if (j < (W_QKV + W_PRJ) / 2)       { in = s ? rpj : spj; N = Cc;     j -= W_QKV / 2; }
    else if (j < (W_QKV + W_PRJ + W_FC1)/2) { in = s ? r1 : s1;   N = DFF;    j -= (W_QKV + W_PRJ) / 2; }
    else                                    { in = s ? r2 : s2;   N = Cc;     j -= (W_QKV + W_PRJ + W_FC1) / 2; }

    int kp = j / N, ps = j - kp * N;
    int p = ps & 31;
    int n = (ps & ~31) + ((p & 3) << 3) + (p >> 2);
    float lo = in[(size_t)(2 * kp) * N + n];
    float hi = in[(size_t)(2 * kp + 1) * N + n];
    __half2 h = __floats2half2_rn(lo, hi);
    out[i] = *(uint32_t*)&h;
}

// ============================================================================
// fused latents = sdpa(latents, concat(x,y), concat(x,y), C^-0.5)
// ============================================================================
__global__ void fuse_latents_kernel(const float* __restrict__ x,
                                    const float* __restrict__ y,
                                    const float* __restrict__ lat,
                                    float* __restrict__ fused)
{
    const int b = blockIdx.x;
    const int tid = threadIdx.x, lane = tid & 31, w = tid >> 5;

    __shared__ float slat[Ll * Cc];
    __shared__ float s[Ll][NCAT];

    for (int i = tid; i < Ll * Cc; i += 256) slat[i] = lat[i];
    __syncthreads();

    const float scale = 0.03608439182435161f;  // 1/sqrt(768)

    for (int n = w; n < NCAT; n += 8) {
        const float* row = (n < Nn) ? x + (size_t)(b * Nn + n) * Cc
                                    : y + (size_t)(b * Nn + (n - Nn)) * Cc;
        float a0 = 0.f, a1 = 0.f, a2 = 0.f, a3 = 0.f;
        for (int c = lane; c < Cc; c += 32) {
            float v = row[c];
            a0 += slat[c] * v;
            a1 += slat[Cc + c] * v;
            a2 += slat[2 * Cc + c] * v;
            a3 += slat[3 * Cc + c] * v;
        }
        #pragma unroll
        for (int o = 16; o; o >>= 1) {
            a0 += __shfl_xor_sync(0xffffffffu, a0, o);
            a1 += __shfl_xor_sync(0xffffffffu, a1, o);
            a2 += __shfl_xor_sync(0xffffffffu, a2, o);
            a3 += __shfl_xor_sync(0xffffffffu, a3, o);
        }
        if (lane == 0) {
            s[0][n] = a0 * scale; s[1][n] = a1 * scale;
            s[2][n] = a2 * scale; s[3][n] = a3 * scale;
        }
    }
    __syncthreads();

    if (w < Ll) {
        float mx = -INFINITY;
        for (int n = lane; n < NCAT; n += 32) mx = fmaxf(mx, s[w][n]);
        #pragma unroll
        for (int o = 16; o; o >>= 1) mx = fmaxf(mx, __shfl_xor_sync(0xffffffffu, mx, o));
        float sum = 0.f;
        for (int n = lane; n < NCAT; n += 32) {
            float e = __expf(s[w][n] - mx);
            s[w][n] = e;
            sum += e;
        }
        #pragma unroll
        for (int o = 16; o; o >>= 1) sum += __shfl_xor_sync(0xffffffffu, sum, o);
        const float inv = 1.f / sum;
        for (int n = lane; n < NCAT; n += 32) s[w][n] *= inv;
    }
    __syncthreads();

    float acc[Ll][3];
    #pragma unroll
    for (int l = 0; l < Ll; l++) { acc[l][0] = acc[l][1] = acc[l][2] = 0.f; }

    const float* xb = x + (size_t)b * Nn * Cc;
    const float* yb = y + (size_t)b * Nn * Cc;
    #pragma unroll 2
    for (int n = 0; n < Nn; n++) {
        const float* row = xb + (size_t)n * Cc;
        float v0 = row[tid], v1 = row[tid + 256], v2 = row[tid + 512];
        #pragma unroll
        for (int l = 0; l < Ll; l++) {
            float sl = s[l][n];
            acc[l][0] += sl * v0; acc[l][1] += sl * v1; acc[l][2] += sl * v2;
        }
    }
    #pragma unroll 2
    for (int n = 0; n < Nn; n++) {
        const float* row = yb + (size_t)n * Cc;
        float v0 = row[tid], v1 = row[tid + 256], v2 = row[tid + 512];
        #pragma unroll
        for (int l = 0; l < Ll; l++) {
            float sl = s[l][Nn + n];
            acc[l][0] += sl * v0; acc[l][1] += sl * v1; acc[l][2] += sl * v2;
        }
    }
    #pragma unroll
    for (int l = 0; l < Ll; l++) {
        float* fp = fused + (size_t)(b * Ll + l) * Cc;
        fp[tid] = acc[l][0]; fp[tid + 256] = acc[l][1]; fp[tid + 512] = acc[l][2];
    }
}

// ============================================================================
// FUSED: out = in + scale * sdpa(in, fused, fused, C^-0.5);  h = LN1(out) half
// ============================================================================
__global__ void cross_attend_ln_kernel(const float* __restrict__ x,
                                       const float* __restrict__ y,
                                       const float* __restrict__ fused,
                                       const float* __restrict__ scale_a,
                                       const float* __restrict__ scale_v,
                                       const float* __restrict__ g0, const float* __restrict__ b0,
                                       const float* __restrict__ g1, const float* __restrict__ b1,
                                       float* __restrict__ outb,
                                       __half* __restrict__ hb)
{
    const int row = blockIdx.x;
    const int b = row / Nn;
    const int z = blockIdx.y;
    const int tid = threadIdx.x, lane = tid & 31, w = tid >> 5;

    const float* in = (z ? y : x) + (size_t)row * Cc;
    float* out = outb + ((size_t)z * ROWS + row) * Cc;
    __half* hout = hb + ((size_t)z * ROWS + row) * Cc;
    const float sc = z ? *scale_v : *scale_a;
    const float* g   = z ? g1 : g0;
    const float* bta = z ? b1 : b0;
    const float* f = fused + (size_t)b * Ll * Cc;

    __shared__ float red[32];
    __shared__ float w4[Ll];
    __shared__ float sred[8];

    const float v0 = in[tid], v1 = in[tid + 256], v2 = in[tid + 512];

    float p[4];
    #pragma unroll
    for (int l = 0; l < Ll; l++) {
        const float* fl = f + l * Cc;
        p[l] = v0 * fl[tid] + v1 * fl[tid + 256] + v2 * fl[tid + 512];
    }
    #pragma unroll
    for (int o = 16; o; o >>= 1) {
        p[0] += __shfl_xor_sync(0xffffffffu, p[0], o);
        p[1] += __shfl_xor_sync(0xffffffffu, p[1], o);
        p[2] += __shfl_xor_sync(0xffffffffu, p[2], o);
        p[3] += __shfl_xor_sync(0xffffffffu, p[3], o);
    }
    if (lane == 0) {
        red[w * 4 + 0] = p[0]; red[w * 4 + 1] = p[1];
        red[w * 4 + 2] = p[2]; red[w * 4 + 3] = p[3];
    }
    __syncthreads();
    if (tid == 0) {
        float t[4] = {0.f, 0.f, 0.f, 0.f};
        #pragma unroll
        for (int i = 0; i < 8; i++) {
            t[0] += red[i * 4]; t[1] += red[i * 4 + 1];
            t[2] += red[i * 4 + 2]; t[3] += red[i * 4 + 3];
        }
        const float scale = 0.03608439182435161f;
        float s0 = t[0] * scale, s1 = t[1] * scale, s2 = t[2] * scale, s3 = t[3] * scale;
        float mx = fmaxf(fmaxf(s0, s1), fmaxf(s2, s3));
        float e0 = __expf(s0 - mx), e1 = __expf(s1 - mx);
        float e2 = __expf(s2 - mx), e3 = __expf(s3 - mx);
        float inv = 1.f / (e0 + e1 + e2 + e3);
        w4[0] = e0 * inv; w4[1] = e1 * inv; w4[2] = e2 * inv; w4[3] = e3 * inv;
    }
    __syncthreads();

    const float a0 = w4[0], a1 = w4[1], a2 = w4[2], a3 = w4[3];
    float o0 = v0 + sc * (a0 * f[tid]       + a1 * f[Cc + tid]       + a2 * f[2 * Cc + tid]       + a3 * f[3 * Cc + tid]);
    float o1 = v1 + sc * (a0 * f[tid + 256] + a1 * f[Cc + tid + 256] + a2 * f[2 * Cc + tid + 256] + a3 * f[3 * Cc + tid + 256]);
    float o2 = v2 + sc * (a0 * f[tid + 512] + a1 * f[Cc + tid + 512] + a2 * f[2 * Cc + tid + 512] + a3 * f[3 * Cc + tid + 512]);
    out[tid] = o0; out[tid + 256] = o1; out[tid + 512] = o2;

    float sum = o0 + o1 + o2;
    #pragma unroll
    for (int o = 16; o; o >>= 1) sum += __shfl_xor_sync(0xffffffffu, sum, o);
    if (lane == 0) sred[w] = sum;
    __syncthreads();
    float mean = 0.f;
    #pragma unroll
    for (int i = 0; i < 8; i++) mean += sred[i];
    mean *= (1.f / Cc);
    __syncthreads();

    float d0 = o0 - mean, d1 = o1 - mean, d2 = o2 - mean;
    float var = d0 * d0 + d1 * d1 + d2 * d2;
    #pragma unroll
    for (int o = 16; o; o >>= 1) var += __shfl_xor_sync(0xffffffffu, var, o);
    if (lane == 0) sred[w] = var;
    __syncthreads();
    float vs = 0.f;
    #pragma unroll
    for (int i = 0; i < 8; i++) vs += sred[i];
    const float rstd = rsqrtf(vs * (1.f / Cc) + 1e-6f);

    hout[permA(tid)]       = __float2half_rn(d0 * rstd * g[tid]       + bta[tid]);
    hout[permA(tid + 256)] = __float2half_rn(d1 * rstd * g[tid + 256] + bta[tid + 256]);
    hout[permA(tid + 512)] = __float2half_rn(d2 * rstd * g[tid + 512] + bta[tid + 512]);
}

// ============================================================================
// LayerNorm (LN2)
// ============================================================================
__global__ void ln_kernel(const float* __restrict__ inb,
                          const float* __restrict__ g0, const float* __restrict__ b0,
                          const float* __restrict__ g1, const float* __restrict__ b1,
                          __half* __restrict__ outb)
{
    const int z = blockIdx.y;
    const int row = blockIdx.x;
    const int tid = threadIdx.x, lane = tid & 31, w = tid >> 5;
    const float* g   = z ? g1 : g0;
    const float* bta = z ? b1 : b0;
    const float* ip = inb  + ((size_t)z * ROWS + row) * Cc;
    __half*      op = outb + ((size_t)z * ROWS + row) * Cc;

    __shared__ float sred[8];

    float v0 = ip[tid], v1 = ip[tid + 256], v2 = ip[tid + 512];
    float sum = v0 + v1 + v2;
    #pragma unroll
    for (int o = 16; o; o >>= 1) sum += __shfl_xor_sync(0xffffffffu, sum, o);
    if (lane == 0) sred[w] = sum;
    __syncthreads();
    float mean = 0.f;
    #pragma unroll
    for (int i = 0; i < 8; i++) mean += sred[i];
    mean *= (1.f / Cc);
    __syncthreads();

    float d0 = v0 - mean, d1 = v1 - mean, d2 = v2 - mean;
    float var = d0 * d0 + d1 * d1 + d2 * d2;
    #pragma unroll
    for (int o = 16; o; o >>= 1) var += __shfl_xor_sync(0xffffffffu, var, o);
    if (lane == 0) sred[w] = var;
    __syncthreads();
    float vs = 0.f;
    #pragma unroll
    for (int i = 0; i < 8; i++) vs += sred[i];
    const float rstd = rsqrtf(vs * (1.f / Cc) + 1e-6f);

    op[permA(tid)]       = __float2half_rn(d0 * rstd * g[tid]       + bta[tid]);
    op[permA(tid + 256)] = __float2half_rn(d1 * rstd * g[tid + 256] + bta[tid + 256]);
    op[permA(tid + 512)] = __float2half_rn(d2 * rstd * g[tid + 512] + bta[tid + 512]);
}

// ============================================================================
// FP16 tensor-core GEMM (R14/R16-measured best): 128x128 block, 8 warps (2x4)
// at 64x32, m16n8k16, fp32 acc. Stage = 2 k-tiles (K-step 32), 3 stages /
// prefetch distance 2, race-free tail, cp.async.cg, 2 CTAs/SM.
// EPI: 0 = bias f32, 1 = bias+gelu half permA, 2 = bias+residual f32,
//      3 = bias half natural (qkv).
// ============================================================================
constexpr int LDBW = 136;
constexpr int A_TILE_H = 128 * 16;
constexpr int B_TILE_W = 8 * LDBW;
constexpr int A_TILE_BYTES = A_TILE_H * 2;        // 4096
constexpr int B_TILE_BYTES = B_TILE_W * 4;        // 4352
constexpr int A_STG_BYTES = 2 * A_TILE_BYTES;     // 8192
constexpr int B_STG_BYTES = 2 * B_TILE_BYTES;     // 8704
constexpr int STAGES = 3;
constexpr int GEMM_SMEM = STAGES * (A_STG_BYTES + B_STG_BYTES);  // 50688

__device__ __forceinline__ void cp_async16(uint32_t s, const void* g) {
    asm volatile("cp.async.cg.shared.global [%0], [%1], 16;" :: "r"(s), "l"(g));
}
__device__ __forceinline__ void cp_commit() {
    asm volatile("cp.async.commit_group;");
}
template<int N>
__device__ __forceinline__ void cp_wait() {
    asm volatile("cp.async.wait_group %0;" :: "n"(N));
}

template<int EPI>
__global__ __launch_bounds__(256, 2)
void h16_gemm_kernel(const __half* __restrict__ Abase, size_t strideA,
                     const uint32_t* __restrict__ W0, const uint32_t* __restrict__ W1,
                     const float* __restrict__ bias0, const float* __restrict__ bias1,
                     const float* __restrict__ resbase,
                     void* __restrict__ Cbase, size_t strideC,
                     int M, int N, int K)
{
    extern __shared__ char smem[];
    char* Ar = smem;
    char* Br = smem + STAGES * A_STG_BYTES;

    const int z = blockIdx.z;
    const __half* A     = Abase + (size_t)z * strideA;
    const uint32_t* Wm  = z ? W1 : W0;
    const float* bias   = z ? bias1 : bias0;
    const float* res    = (EPI == 2) ? resbase + (size_t)z * strideC : nullptr;
    float*  Cf = (float*)Cbase + (size_t)z * strideC;
    __half* Ch = (__half*)Cbase + (size_t)z * strideC;

    const int tid  = threadIdx.x;
    const int lane = tid & 31;
    const int w    = tid >> 5;
    const int wm   = w >> 2;
    const int wn   = w & 3;
    const int gid  = lane >> 2;
    const int tig  = lane & 3;

    const int bm = blockIdx.y * 128;
    const int bn = blockIdx.x * 128;

    float acc[4][4][4];
    #pragma unroll
    for (int i = 0; i < 4; i++)
        #pragma unroll
        for (int j = 0; j < 4; j++)
            #pragma unroll
            for (int q = 0; q < 4; q++) acc[i][j][q] = 0.f;

    const int arow = tid >> 1;
    const int achk = tid & 1;
    const int bkp  = tid >> 5;
    const int bcol = (tid & 31) * 4;

    const __half* Ap = A + (size_t)(bm + arow) * K + achk * 8;
    const uint32_t* Bp = Wm + (size_t)bkp * N + bn + bcol;

    const uint32_t sA = (uint32_t)__cvta_generic_to_shared(Ar) + arow * 32 + achk * 16;
    const uint32_t sB = (uint32_t)__cvta_generic_to_shared(Br) + (bkp * LDBW + bcol) * 4;

    const int aoff = ((wm * 64 + gid) * 16 + tig * 4) * 2;
    const int boff = (wn * 32 + gid * 4) * 4;

    const int KT2 = K / 32;

    auto load_stage = [&](int k2, int stg) {
        #pragma unroll
        for (int sub = 0; sub < 2; sub++) {
            const int kt = k2 * 2 + sub;
            cp_async16(sA + stg * A_STG_BYTES + sub * A_TILE_BYTES, Ap + kt * 16);
            cp_async16(sB + stg * B_STG_BYTES + sub * B_TILE_BYTES, Bp + (size_t)kt * 8 * N);
        }
        cp_commit();
    };

    load_stage(0, 0);
    load_stage(1, 1);
    cp_wait<1>();
    __syncthreads();

    int buf = 0;
    for (int k2 = 0; k2 < KT2; k2++) {
        const bool pf = (k2 + 2 < KT2);
        if (pf) {
            int s = buf + 2; if (s >= STAGES) s -= STAGES;
            load_stage(k2 + 2, s);
        }

        const char* Abase_s = Ar + buf * A_STG_BYTES + aoff;
        const char* Bbase_s = Br + buf * B_STG_BYTES + boff;
        #pragma unroll
        for (int sub = 0; sub < 2; sub++) {
            const __half*   Aw = (const __half*)(Abase_s + sub * A_TILE_BYTES);
            const uint32_t* Bw = (const uint32_t*)(Bbase_s + sub * B_TILE_BYTES);

            uint4 bq0 = *(const uint4*)(Bw + tig * LDBW);
            uint4 bq1 = *(const uint4*)(Bw + (tig + 4) * LDBW);

            #pragma unroll
            for (int i = 0; i < 4; i++) {
                uint2 aLo = *(const uint2*)(Aw + i * 256);
                uint2 aHi = *(const uint2*)(Aw + i * 256 + 128);
                mma_f16(acc[i][0], aLo.x, aHi.x, aLo.y, aHi.y, bq0.x, bq1.x);
                mma_f16(acc[i][1], aLo.x, aHi.x, aLo.y, aHi.y, bq0.y, bq1.y);
                mma_f16(acc[i][2], aLo.x, aHi.x, aLo.y, aHi.y, bq0.z, bq1.z);
                mma_f16(acc[i][3], aLo.x, aHi.x, aLo.y, aHi.y, bq0.w, bq1.w);
            }
        }

        if (k2 + 1 < KT2) {
            if (pf) cp_wait<1>(); else cp_wait<0>();   // race-free tail
            __syncthreads();
            buf = (buf + 1 < STAGES) ? buf + 1 : 0;
        }
    }

    #pragma unroll
    for (int i = 0; i < 4; i++) {
        const int r0 = bm + wm * 64 + i * 16 + gid;
        #pragma unroll
        for (int j = 0; j < 4; j++) {
            const int c = bn + wn * 32 + j * 8 + tig * 2;
            const float b0 = bias[c], b1 = bias[c + 1];

            float v0 = acc[i][j][0] + b0;
            float v1 = acc[i][j][1] + b1;
            float v2 = acc[i][j][2] + b0;
            float v3 = acc[i][j][3] + b1;
            if (EPI == 1) {
                v0 = v0 * 0.5f * (1.f + erff(v0 * 0.70710678118654752f));
                v1 = v1 * 0.5f * (1.f + erff(v1 * 0.70710678118654752f));
                v2 = v2 * 0.5f * (1.f + erff(v2 * 0.70710678118654752f));
                v3 = v3 * 0.5f * (1.f + erff(v3 * 0.70710678118654752f));
                const int pa = permA(c);
                *(__half2*)&Ch[(size_t)r0 * N + pa]       = __floats2half2_rn(v0, v1);
                *(__half2*)&Ch[(size_t)(r0 + 8) * N + pa] = __floats2half2_rn(v2, v3);
            } else if (EPI == 3) {
                *(__half2*)&Ch[(size_t)r0 * N + c]       = __floats2half2_rn(v0, v1);
                *(__half2*)&Ch[(size_t)(r0 + 8) * N + c] = __floats2half2_rn(v2, v3);
            } else {
                if (EPI == 2) {
                    const float* r = res + (size_t)r0 * N + c;
                    v0 += r[0]; v1 += r[1];
                    const float* r2 = res + (size_t)(r0 + 8) * N + c;
                    v2 += r2[0]; v3 += r2[1];
                }
                *(float2*)&Cf[(size_t)r0 * N + c]       = make_float2(v0, v1);
                *(float2*)&Cf[(size_t)(r0 + 8) * N + c] = make_float2(v2, v3);
            }
        }
    }
}

// ============================================================================
// Tensor-core attention: one block per (b, head, stream), 256 threads.
// S = (Q*0.125) K^T via m16n8k16 (fp32 acc); softmax in registers
// (quad-shuffle row reductions, masked cols >= 196); P packed to half in
// A-fragment layout (acc layout == A layout identity); O = P V via mma.
// Smem: Qp[32][216] u32 (half2 d-pairs, col = m), Kp[32][216] u32 (col = n),
// Vp[104][72] u32 (half2 n-pairs, col = j). All bank-conflict-free.
// Output half, k-permuted (feeds proj GEMM A).
// ============================================================================
constexpr int QP_STRIDE = 216;
constexpr int KP_STRIDE = 216;
constexpr int VP_STRIDE = 72;
constexpr int QP_WORDS = 32 * QP_STRIDE;
constexpr int KP_WORDS = 32 * KP_STRIDE;
constexpr int VP_WORDS = 104 * VP_STRIDE;
constexpr int ATTN_SMEM = (QP_WORDS + KP_WORDS + VP_WORDS) * 4;  // 85248

__global__ void attn_kernel(const __half* __restrict__ qkvb_, __half* __restrict__ ob_)
{
    extern __shared__ uint32_t smw[];
    uint32_t* Qp = smw;
    uint32_t* Kp = Qp + QP_WORDS;
    uint32_t* Vp = Kp + KP_WORDS;

    const int z = blockIdx.y;
    const int bh = blockIdx.x;
    const int b = bh / Hh, hh = bh % Hh;
    const int tid = threadIdx.x, lane = tid & 31;
    const int w = tid >> 5;
    const int gid = lane >> 2, tig = lane & 3;

    const __half* qkvb = qkvb_ + (size_t)z * ROWS * 3 * Cc + (size_t)b * Nn * (3 * Cc);
    __half* o = ob_ + (size_t)z * ROWS * Cc;

    // ---- fill Qp (scaled 0.125) and Kp: thread per row m ----
    const __half2 hscale = __float2half2_rn(0.125f);
    for (int m = tid; m < 208; m += 256) {
        uint32_t vq[32], vk[32];
        if (m < Nn) {
            const uint32_t* qr = (const uint32_t*)(qkvb + (size_t)m * (3 * Cc) + hh * HD);
            const uint32_t* kr = qr + Cc / 2;
            #pragma unroll
            for (int i = 0; i < 32; i++) {
                __half2 qh = *(const __half2*)&qr[i];
                qh = __hmul2(qh, hscale);
                vq[i] = *(uint32_t*)&qh;
                vk[i] = kr[i];
            }
        } else {
            #pragma unroll
            for (int i = 0; i < 32; i++) { vq[i] = 0u; vk[i] = 0u; }
        }
        #pragma unroll
        for (int i = 0; i < 32; i++) {
            Qp[i * QP_STRIDE + m] = vq[i];
            Kp[i * KP_STRIDE + m] = vk[i];
        }
    }

    // ---- fill Vp: thread per n-pair np ----
    for (int np = tid; np < 104; np += 256) {
        uint32_t vv[64];
        if (np < Nn / 2) {
            const __half2* r0 = (const __half2*)(qkvb + (size_t)(2 * np)     * (3 * Cc) + 2 * Cc + hh * HD);
            const __half2* r1 = (const __half2*)(qkvb + (size_t)(2 * np + 1) * (3 * Cc) + 2 * Cc + hh * HD);
            #pragma unroll
            for (int k = 0; k < 32; k++) {
                __half2 a = r0[k], c = r1[k];
                __half2 lo = __lows2half2(a, c);
                __half2 hi = __highs2half2(a, c);
                vv[2 * k]     = *(uint32_t*)&lo;
                vv[2 * k + 1] = *(uint32_t*)&hi;
            }
        } else {
            #pragma unroll
            for (int k = 0; k < 64; k++) vv[k] = 0u;
        }
        #pragma unroll
        for (int k = 0; k < 64; k++) Vp[np * VP_STRIDE + k] = vv[k];
    }
    __syncthreads();

    // ---- per-warp 16-row tiles (13 tiles over 8 warps) ----
    for (int tile = w; tile < 13; tile += 8) {
        const int m0 = tile * 16;

        // S = Q K^T : acc over 25 n-tiles (cols 0..199)
        float acc[25][4];
        #pragma unroll
        for (int j = 0; j < 25; j++)
            #pragma unroll
            for (int q = 0; q < 4; q++) acc[j][q] = 0.f;

        #pragma unroll
        for (int c = 0; c < 4; c++) {
            const uint32_t* qa = Qp + (8 * c + tig) * QP_STRIDE + m0 + gid;
            const uint32_t a0 = qa[0];
            const uint32_t a1 = qa[8];
            const uint32_t a2 = qa[4 * QP_STRIDE];
            const uint32_t a3 = qa[4 * QP_STRIDE + 8];
            const uint32_t* kb = Kp + (8 * c + tig) * KP_STRIDE + gid;
            #pragma unroll
            for (int j = 0; j < 25; j++) {
                const uint32_t b0 = kb[8 * j];
                const uint32_t b1 = kb[4 * KP_STRIDE + 8 * j];
                mma_f16(acc[j], a0, a1, a2, a3, b0, b1);
            }
        }

        // masked softmax over rows m0+gid, m0+gid+8
        float mx0 = -1e30f, mx1 = -1e30f;
        #pragma unroll
        for (int j = 0; j < 25; j++) {
            if (8 * j + 2 * tig < Nn)     { mx0 = fmaxf(mx0, acc[j][0]); mx1 = fmaxf(mx1, acc[j][2]); }
            if (8 * j + 2 * tig + 1 < Nn) { mx0 = fmaxf(mx0, acc[j][1]); mx1 = fmaxf(mx1, acc[j][3]); }
        }
        mx0 = fmaxf(mx0, __shfl_xor_sync(0xffffffffu, mx0, 1));
        mx0 = fmaxf(mx0, __shfl_xor_sync(0xffffffffu, mx0, 2));
        mx1 = fmaxf(mx1, __shfl_xor_sync(0xffffffffu, mx1, 1));
        mx1 = fmaxf(mx1, __shfl_xor_sync(0xffffffffu, mx1, 2));

        float s0 = 0.f, s1 = 0.f;
        uint32_t pk[13][4];
        #pragma unroll
        for (int j = 0; j < 25; j++) {
            const bool ok0 = (8 * j + 2 * tig)     < Nn;
            const bool ok1 = (8 * j + 2 * tig + 1) < Nn;
            float e0 = ok0 ? __expf(acc[j][0] - mx0) : 0.f;
            float e1 = ok1 ? __expf(acc[j][1] - mx0) : 0.f;
            float e2 = ok0 ? __expf(acc[j][2] - mx1) : 0.f;
            float e3 = ok1 ? __expf(acc[j][3] - mx1) : 0.f;
            s0 += e0 + e1;
            s1 += e2 + e3;
            __half2 h01 = __floats2half2_rn(e0, e1);
            __half2 h23 = __floats2half2_rn(e2, e3);
            if ((j & 1) == 0) { pk[j >> 1][0] = *(uint32_t*)&h01; pk[j >> 1][1] = *(uint32_t*)&h23; }
            else              { pk[j >> 1][2] = *(uint32_t*)&h01; pk[j >> 1][3] = *(uint32_t*)&h23; }
        }
        pk[12][2] = 0u;  // n-tile 25 (cols 200..207) fully masked
        pk[12][3] = 0u;

        s0 += __shfl_xor_sync(0xffffffffu, s0, 1);
        s0 += __shfl_xor_sync(0xffffffffu, s0, 2);
        s1 += __shfl_xor_sync(0xffffffffu, s1, 1);
        s1 += __shfl_xor_sync(0xffffffffu, s1, 2);
        const float inv0 = 1.f / s0, inv1 = 1.f / s1;

        // O = P V
        float oacc[8][4];
        #pragma unroll
        for (int jj = 0; jj < 8; jj++)
            #pragma unroll
            for (int q = 0; q < 4; q++) oacc[jj][q] = 0.f;

        #pragma unroll
        for (int c = 0; c < 13; c++) {
            const uint32_t* vb = Vp + (8 * c + tig) * VP_STRIDE + gid;
            #pragma unroll
            for (int jj = 0; jj < 8; jj++) {
                const uint32_t b0 = vb[8 * jj];
                const uint32_t b1 = vb[4 * VP_STRIDE + 8 * jj];
                mma_f16(oacc[jj], pk[c][0], pk[c][1], pk[c][2], pk[c][3], b0, b1);
            }
        }

        // epilogue: normalize, store half, k-permuted
        const int m_lo = m0 + gid, m_hi = m0 + gid + 8;
        #pragma unroll
        for (int jj = 0; jj < 8; jj++) {
            const int cl = hh * HD + 8 * jj + 2 * tig;
            const int pa = permA(cl);
            if (m_lo < Nn) {
                __half* op = o + (size_t)(b * Nn + m_lo) * Cc;
                *(__half2*)&op[pa] = __floats2half2_rn(oacc[jj][0] * inv0, oacc[jj][1] * inv0);
            }
            if (m_hi < Nn) {
                __half* op = o + (size_t)(b * Nn + m_hi) * Cc;
                *(__half2*)&op[pa] = __floats2half2_rn(oacc[jj][2] * inv1, oacc[jj][3] * inv1);
            }
        }
    }
}

// ============================================================================
// host launcher
// ============================================================================
extern "C" void kernel_launch(void* const* d_in, const int* in_sizes, int n_in,
                              void* d_out, int out_size)
{
    const float* x        = (const float*)d_in[0];
    const float* y        = (const float*)d_in[1];
    const float* latents  = (const float*)d_in[2];
    const float* scale_a  = (const float*)d_in[3];
    const float* scale_v  = (const float*)d_in[4];

    const float* sp[12];
    const float* rp[12];
    for (int i = 0; i < 12; i++) { sp[i] = (const float*)d_in[5 + i]; rp[i] = (const float*)d_in[17 + i]; }

    float* outx = (float*)d_out;

    float *fused;
    __half *hbuf, *qkvbuf, *obuf, *mlpbuf;
    uint32_t* wbuf;
    cudaGetSymbolAddress((void**)&fused,  g_fused);
    cudaGetSymbolAddress((void**)&hbuf,   g_h);
    cudaGetSymbolAddress((void**)&qkvbuf, g_qkv);
    cudaGetSymbolAddress((void**)&obuf,   g_o);
    cudaGetSymbolAddress((void**)&mlpbuf, g_mlp);
    cudaGetSymbolAddress((void**)&wbuf,   g_w);

    // smem opt-in (GEMM 50688 B, attn 85248 B > 48 KB default)
    cudaFuncSetAttribute(attn_kernel, cudaFuncAttributeMaxDynamicSharedMemorySize, ATTN_SMEM);
    cudaFuncSetAttribute(h16_gemm_kernel<0>, cudaFuncAttributeMaxDynamicSharedMemorySize, GEMM_SMEM);
    cudaFuncSetAttribute(h16_gemm_kernel<1>, cudaFuncAttributeMaxDynamicSharedMemorySize, GEMM_SMEM);
    cudaFuncSetAttribute(h16_gemm_kernel<2>, cudaFuncAttributeMaxDynamicSharedMemorySize, GEMM_SMEM);
    cudaFuncSetAttribute(h16_gemm_kernel<3>, cudaFuncAttributeMaxDynamicSharedMemorySize, GEMM_SMEM);

    const size_t sC   = (size_t)ROWS * Cc;
    const size_t sQKV = (size_t)ROWS * 3 * Cc;
    const size_t sMLP = (size_t)ROWS * DFF;

    uint32_t* wq[2]; uint32_t* wp[2]; uint32_t* w1[2]; uint32_t* w2[2];
    for (int s = 0; s < 2; s++) {
        uint32_t* base = wbuf + (size_t)s * W_HALF;
        wq[s] = base;
        wp[s] = base + W_QKV / 2;
        w1[s] = base + (W_QKV + W_PRJ) / 2;
        w2[s] = base + (W_QKV + W_PRJ + W_FC1) / 2;
    }

    // launch order: #4 = qkv GEMM (ncu captures the 4th launch)
    round_w_all_kernel<<<(W_ALL + 255) / 256, 256>>>(
        sp[2], sp[4], sp[8], sp[10], rp[2], rp[4], rp[8], rp[10], wbuf);

    fuse_latents_kernel<<<Bb, 256>>>(x, y, latents, fused);

    cross_attend_ln_kernel<<<dim3(ROWS, 2), 256>>>(
        x, y, fused, scale_a, scale_v,
        sp[0], sp[1], rp[0], rp[1], outx, hbuf);

    h16_gemm_kernel<3><<<dim3(3 * Cc / 128, ROWS / 128, 2), 256, GEMM_SMEM>>>(
        hbuf, sC, wq[0], wq[1], sp[3], rp[3], nullptr, qkvbuf, sQKV,
        ROWS, 3 * Cc, Cc);

    attn_kernel<<<dim3(Bb * Hh, 2), 256, ATTN_SMEM>>>(qkvbuf, obuf);

    h16_gemm_kernel<2><<<dim3(Cc / 128, ROWS / 128, 2), 256, GEMM_SMEM>>>(
        obuf, sC, wp[0], wp[1], sp[5], rp[5], outx, outx, sC,
        ROWS, Cc, Cc);

    ln_kernel<<<dim3(ROWS, 2), 256>>>(outx, sp[6], sp[7], rp[6], rp[7], hbuf);

    h16_gemm_kernel<1><<<dim3(DFF / 128, ROWS / 128, 2), 256, GEMM_SMEM>>>(
        hbuf, sC, w1[0], w1[1], sp[9], rp[9], nullptr, mlpbuf, sMLP,
        ROWS, DFF, Cc);

    h16_gemm_kernel<2><<<dim3(Cc / 128, ROWS / 128, 2), 256, GEMM_SMEM>>>(
        mlpbuf, sMLP, w2[0], w2[1], sp[11], rp[11], outx, outx, sC,
        ROWS, Cc, DFF);
}